// round 6
// baseline (speedup 1.0000x reference)
#include <cuda_runtime.h>
#include <cstdint>

#define SEQ 4096
#define DM  768
#define NH  12
#define HD  64

// ---------------- scratch (no allocations allowed) ----------------
__device__ float g_Q[SEQ * DM];
__device__ float g_K[SEQ * DM];
__device__ float g_V[SEQ * DM];
__device__ float g_att[SEQ * DM];

// ---------------- helpers ----------------
__device__ __forceinline__ uint32_t f2tf32(float x) {
    uint32_t y;
    asm("cvt.rna.tf32.f32 %0, %1;" : "=r"(y) : "f"(x));
    return y;
}
__device__ __forceinline__ float fexp2(float x) {
    float y;
    asm("ex2.approx.ftz.f32 %0, %1;" : "=f"(y) : "f"(x));
    return y;
}
// D += A*B  (m16n8k8 tf32, fp32 accumulate)
__device__ __forceinline__ void mma8(float* d,
                                     uint32_t a0, uint32_t a1, uint32_t a2, uint32_t a3,
                                     uint32_t b0, uint32_t b1) {
    asm volatile(
        "mma.sync.aligned.m16n8k8.row.col.f32.tf32.tf32.f32 "
        "{%0,%1,%2,%3}, {%4,%5,%6,%7}, {%8,%9}, {%0,%1,%2,%3};"
        : "+f"(d[0]), "+f"(d[1]), "+f"(d[2]), "+f"(d[3])
        : "r"(a0), "r"(a1), "r"(a2), "r"(a3), "r"(b0), "r"(b1));
}

// ================= GEMM: C[M,N] = A[M,K] * B[N,K]^T  (tf32 mma.sync) =================
// 128x128x32 tile, 8 warps, DOUBLE-BUFFERED smem: 1 sync per k-tile.
#define GS 36                 // 36 % 32 == 4 -> frag LDS conflict-free
#define GBUF (128 * GS)       // words per operand buffer (4608)
#define GEMM_SMEM_BYTES (4 * GBUF * 4)   // 2 bufs x (A+B) = 73728 B

__global__ __launch_bounds__(256, 2)
void gemm_tc(const float* __restrict__ A,
             const float* __restrict__ B0, const float* __restrict__ B1, const float* __restrict__ B2,
             float* __restrict__ C0, float* __restrict__ C1, float* __restrict__ C2,
             int M, int N, int K)
{
    const float* B = (blockIdx.z == 0) ? B0 : ((blockIdx.z == 1) ? B1 : B2);
    float*       C = (blockIdx.z == 0) ? C0 : ((blockIdx.z == 1) ? C1 : C2);

    extern __shared__ uint32_t gsm[];
    uint32_t* As = gsm;              // [2][GBUF]
    uint32_t* Bs = gsm + 2 * GBUF;   // [2][GBUF]

    const int tid  = threadIdx.x;
    const int wid  = tid >> 5;
    const int lane = tid & 31;
    const int g    = lane >> 2;
    const int tg   = lane & 3;
    const int wm   = (wid >> 2) * 64;
    const int wn   = (wid & 3) * 32;
    const int m0   = blockIdx.y * 128;
    const int n0   = blockIdx.x * 128;

    const int lrow = tid >> 1;
    const int lc   = (tid & 1) * 16;
    const float* Ap = A + (size_t)(m0 + lrow) * K + lc;
    const float* Bp = B + (size_t)(n0 + lrow) * K + lc;

    float4 pa[4], pb[4];
#pragma unroll
    for (int i = 0; i < 4; i++) {
        pa[i] = *(const float4*)(Ap + i * 4);
        pb[i] = *(const float4*)(Bp + i * 4);
    }
    // commit tile 0 into buffer 0
#pragma unroll
    for (int i = 0; i < 4; i++) {
        uint4 ua = make_uint4(f2tf32(pa[i].x), f2tf32(pa[i].y), f2tf32(pa[i].z), f2tf32(pa[i].w));
        *(uint4*)&As[lrow * GS + lc + i * 4] = ua;
        uint4 ub = make_uint4(f2tf32(pb[i].x), f2tf32(pb[i].y), f2tf32(pb[i].z), f2tf32(pb[i].w));
        *(uint4*)&Bs[lrow * GS + lc + i * 4] = ub;
    }
    __syncthreads();

    float acc[4][4][4] = {};
    const int T = K / 32;

    for (int t = 0; t < T; t++) {
        const int b = t & 1;
        const uint32_t* Ab = As + b * GBUF;
        const uint32_t* Bb = Bs + b * GBUF;

        if (t + 1 < T) {
#pragma unroll
            for (int i = 0; i < 4; i++) {
                pa[i] = *(const float4*)(Ap + (t + 1) * 32 + i * 4);
                pb[i] = *(const float4*)(Bp + (t + 1) * 32 + i * 4);
            }
        }

#pragma unroll
        for (int ks = 0; ks < 4; ks++) {
            const int k0 = ks * 8;
            uint32_t af[4][4];
#pragma unroll
            for (int mt = 0; mt < 4; mt++) {
                const int r = wm + mt * 16 + g;
                af[mt][0] = Ab[r * GS + k0 + tg];
                af[mt][1] = Ab[(r + 8) * GS + k0 + tg];
                af[mt][2] = Ab[r * GS + k0 + tg + 4];
                af[mt][3] = Ab[(r + 8) * GS + k0 + tg + 4];
            }
#pragma unroll
            for (int nt = 0; nt < 4; nt++) {
                const int rn = wn + nt * 8 + g;
                uint32_t b0 = Bb[rn * GS + k0 + tg];
                uint32_t b1 = Bb[rn * GS + k0 + tg + 4];
#pragma unroll
                for (int mt = 0; mt < 4; mt++)
                    mma8(acc[mt][nt], af[mt][0], af[mt][1], af[mt][2], af[mt][3], b0, b1);
            }
        }

        if (t + 1 < T) {
            uint32_t* An = As + (b ^ 1) * GBUF;
            uint32_t* Bn = Bs + (b ^ 1) * GBUF;
#pragma unroll
            for (int i = 0; i < 4; i++) {
                uint4 ua = make_uint4(f2tf32(pa[i].x), f2tf32(pa[i].y), f2tf32(pa[i].z), f2tf32(pa[i].w));
                *(uint4*)&An[lrow * GS + lc + i * 4] = ua;
                uint4 ub = make_uint4(f2tf32(pb[i].x), f2tf32(pb[i].y), f2tf32(pb[i].z), f2tf32(pb[i].w));
                *(uint4*)&Bn[lrow * GS + lc + i * 4] = ub;
            }
        }
        __syncthreads();
    }

#pragma unroll
    for (int mt = 0; mt < 4; mt++) {
        const int r0 = m0 + wm + mt * 16 + g;
#pragma unroll
        for (int nt = 0; nt < 4; nt++) {
            const int c = n0 + wn + nt * 8 + tg * 2;
            *(float2*)&C[(size_t)r0 * N + c]       = make_float2(acc[mt][nt][0], acc[mt][nt][1]);
            *(float2*)&C[(size_t)(r0 + 8) * N + c] = make_float2(acc[mt][nt][2], acc[mt][nt][3]);
        }
    }
}

// ================= Flash attention v4 =================
// 128-row q-tile, 4 warps x 32 rows, 128 threads, 2 CTAs/SM.
// Double-buffered K/V smem; ONE __syncthreads per KV tile.
// P never goes through smem: PV A-fragments built by quad shuffles.
#define QS_ST 68   // 68 % 32 == 4 : A/B frag pattern conflict-free
#define VS_ST 72   // 72 % 32 == 8 : V b-frag pattern conflict-free
#define KBUF (64 * QS_ST)   // 4352 words per K buffer
#define VBUF (64 * VS_ST)   // 4608 words per V buffer
#define SM_Q  0
#define SM_K  (128 * QS_ST)            // 8704
#define SM_V  (SM_K + 2 * KBUF)        // 17408
#define FLASH_SMEM_WORDS (SM_V + 2 * VBUF)   // 26624 words = 106496 B

__global__ __launch_bounds__(128, 2)
void flash_tc(const float* __restrict__ Qg, const float* __restrict__ Kg,
              const float* __restrict__ Vg, float* __restrict__ O)
{
    extern __shared__ uint32_t sm[];
    uint32_t* Qs = sm + SM_Q;
    uint32_t* Ks = sm + SM_K;
    uint32_t* Vs = sm + SM_V;

    const int qt   = (int)gridDim.x - 1 - blockIdx.x;  // longest blocks first
    const int h    = blockIdx.y;
    const int tid  = threadIdx.x;
    const int lane = tid & 31;
    const int g    = lane >> 2;
    const int tg   = lane & 3;
    const int wm   = (tid >> 5) * 32;   // 4 warps x 32 rows

    // ---- load Q tile (1 row per thread), pre-scaled into base-2 domain ----
    const float sc = 0.125f * 1.4426950408889634f;
    {
        const float* qp = Qg + (size_t)(qt * 128 + tid) * DM + h * HD;
#pragma unroll
        for (int i = 0; i < 16; i++) {
            float4 v = *(const float4*)(qp + i * 4);
            uint4 u = make_uint4(f2tf32(v.x * sc), f2tf32(v.y * sc), f2tf32(v.z * sc), f2tf32(v.w * sc));
            *(uint4*)&Qs[tid * QS_ST + i * 4] = u;
        }
    }

    // ---- K/V loader mapping: 2 threads per row, 32 floats each ----
    const int krow = tid >> 1;
    const int kc   = (tid & 1) * 32;

    float4 pk[8], pv[8];
    {
        const size_t gb = (size_t)krow * DM + h * HD + kc;   // tile 0
#pragma unroll
        for (int i = 0; i < 8; i++) {
            pk[i] = *(const float4*)(Kg + gb + i * 4);
            pv[i] = *(const float4*)(Vg + gb + i * 4);
        }
        // commit tile 0 to buffer 0
#pragma unroll
        for (int i = 0; i < 8; i++) {
            uint4 uk = make_uint4(f2tf32(pk[i].x), f2tf32(pk[i].y), f2tf32(pk[i].z), f2tf32(pk[i].w));
            *(uint4*)&Ks[krow * QS_ST + kc + i * 4] = uk;
            uint4 uv = make_uint4(f2tf32(pv[i].x), f2tf32(pv[i].y), f2tf32(pv[i].z), f2tf32(pv[i].w));
            *(uint4*)&Vs[krow * VS_ST + kc + i * 4] = uv;
        }
    }
    __syncthreads();

    float o[2][8][4] = {};
    float m_[4], l_[4];
#pragma unroll
    for (int i = 0; i < 4; i++) { m_[i] = -1e30f; l_[i] = 0.0f; }

    const int jmax = 2 * qt + 1;

    for (int j = 0; j <= jmax; j++) {
        const int b = j & 1;
        const uint32_t* Kb = Ks + b * KBUF;
        const uint32_t* Vb = Vs + b * VBUF;

        // ---- prefetch next K/V tile (overlaps all compute of this tile) ----
        if (j < jmax) {
            const size_t gb = (size_t)((j + 1) * 64 + krow) * DM + h * HD + kc;
#pragma unroll
            for (int i = 0; i < 8; i++) {
                pk[i] = *(const float4*)(Kg + gb + i * 4);
                pv[i] = *(const float4*)(Vg + gb + i * 4);
            }
        }

        // ---- S = Q K^T ----
        float sv[2][8][4] = {};
#pragma unroll
        for (int ks = 0; ks < 8; ks++) {
            const int k0 = ks * 8;
            uint32_t a[2][4];
#pragma unroll
            for (int mb = 0; mb < 2; mb++) {
                const int r = wm + mb * 16 + g;
                a[mb][0] = Qs[r * QS_ST + k0 + tg];
                a[mb][1] = Qs[(r + 8) * QS_ST + k0 + tg];
                a[mb][2] = Qs[r * QS_ST + k0 + tg + 4];
                a[mb][3] = Qs[(r + 8) * QS_ST + k0 + tg + 4];
            }
#pragma unroll
            for (int nt = 0; nt < 8; nt++) {
                uint32_t b0 = Kb[(nt * 8 + g) * QS_ST + k0 + tg];
                uint32_t b1 = Kb[(nt * 8 + g) * QS_ST + k0 + tg + 4];
                mma8(sv[0][nt], a[0][0], a[0][1], a[0][2], a[0][3], b0, b1);
                mma8(sv[1][nt], a[1][0], a[1][1], a[1][2], a[1][3], b0, b1);
            }
        }

        // ---- causal mask (only last two KV tiles intersect the diagonal) ----
        if (j >= 2 * qt) {
            const int cb = j * 64;
#pragma unroll
            for (int mb = 0; mb < 2; mb++) {
                const int r0 = qt * 128 + wm + mb * 16 + g, r1 = r0 + 8;
#pragma unroll
                for (int nt = 0; nt < 8; nt++) {
#pragma unroll
                    for (int cc = 0; cc < 2; cc++) {
                        const int col = cb + nt * 8 + tg * 2 + cc;
                        if (col > r0) sv[mb][nt][cc]     = -1e30f;
                        if (col > r1) sv[mb][nt][2 + cc] = -1e30f;
                    }
                }
            }
        }

        // ---- online softmax (base-2) ----
#pragma unroll
        for (int mb = 0; mb < 2; mb++) {
            float mx0 = -1e30f, mx1 = -1e30f;
#pragma unroll
            for (int nt = 0; nt < 8; nt++) {
                mx0 = fmaxf(mx0, fmaxf(sv[mb][nt][0], sv[mb][nt][1]));
                mx1 = fmaxf(mx1, fmaxf(sv[mb][nt][2], sv[mb][nt][3]));
            }
            mx0 = fmaxf(mx0, __shfl_xor_sync(0xffffffffu, mx0, 1));
            mx0 = fmaxf(mx0, __shfl_xor_sync(0xffffffffu, mx0, 2));
            mx1 = fmaxf(mx1, __shfl_xor_sync(0xffffffffu, mx1, 1));
            mx1 = fmaxf(mx1, __shfl_xor_sync(0xffffffffu, mx1, 2));

            const int g0 = 2 * mb, g1 = 2 * mb + 1;
            const float mn0 = fmaxf(m_[g0], mx0), mn1 = fmaxf(m_[g1], mx1);
            const float al0 = fexp2(m_[g0] - mn0), al1 = fexp2(m_[g1] - mn1);
            float s0 = 0.0f, s1 = 0.0f;
#pragma unroll
            for (int nt = 0; nt < 8; nt++) {
                sv[mb][nt][0] = fexp2(sv[mb][nt][0] - mn0); s0 += sv[mb][nt][0];
                sv[mb][nt][1] = fexp2(sv[mb][nt][1] - mn0); s0 += sv[mb][nt][1];
                sv[mb][nt][2] = fexp2(sv[mb][nt][2] - mn1); s1 += sv[mb][nt][2];
                sv[mb][nt][3] = fexp2(sv[mb][nt][3] - mn1); s1 += sv[mb][nt][3];
            }
            s0 += __shfl_xor_sync(0xffffffffu, s0, 1);
            s0 += __shfl_xor_sync(0xffffffffu, s0, 2);
            s1 += __shfl_xor_sync(0xffffffffu, s1, 1);
            s1 += __shfl_xor_sync(0xffffffffu, s1, 2);
            l_[g0] = l_[g0] * al0 + s0;  l_[g1] = l_[g1] * al1 + s1;
            m_[g0] = mn0;  m_[g1] = mn1;
#pragma unroll
            for (int nt = 0; nt < 8; nt++) {
                o[mb][nt][0] *= al0; o[mb][nt][1] *= al0;
                o[mb][nt][2] *= al1; o[mb][nt][3] *= al1;
            }
        }

        // ---- O += P V : A-fragments of P built by quad shuffles (no smem) ----
        // P[row, col]: thread (g,tg) holds cols {2tg, 2tg+1} of rows {g, g+8} per n-tile.
        // A-frag for k-chunk kc: col kc*8+tg from lane 4g+(tg>>1), col kc*8+tg+4 from lane+2,
        // element parity tg&1.
        const int src0 = (lane & 28) | (tg >> 1);
        const int src2 = src0 + 2;
        const bool odd = (tg & 1) != 0;
#pragma unroll
        for (int ksb = 0; ksb < 8; ksb++) {
            const int k0 = ksb * 8;
            uint32_t a[2][4];
#pragma unroll
            for (int mb = 0; mb < 2; mb++) {
                uint32_t v0 = f2tf32(sv[mb][ksb][0]);
                uint32_t v1 = f2tf32(sv[mb][ksb][1]);
                uint32_t v2 = f2tf32(sv[mb][ksb][2]);
                uint32_t v3 = f2tf32(sv[mb][ksb][3]);
                uint32_t t0 = __shfl_sync(0xffffffffu, v0, src0);
                uint32_t t1 = __shfl_sync(0xffffffffu, v1, src0);
                uint32_t t2 = __shfl_sync(0xffffffffu, v2, src0);
                uint32_t t3 = __shfl_sync(0xffffffffu, v3, src0);
                uint32_t u0 = __shfl_sync(0xffffffffu, v0, src2);
                uint32_t u1 = __shfl_sync(0xffffffffu, v1, src2);
                uint32_t u2 = __shfl_sync(0xffffffffu, v2, src2);
                uint32_t u3 = __shfl_sync(0xffffffffu, v3, src2);
                a[mb][0] = odd ? t1 : t0;   // P[g,    k0+tg]
                a[mb][1] = odd ? t3 : t2;   // P[g+8,  k0+tg]
                a[mb][2] = odd ? u1 : u0;   // P[g,    k0+tg+4]
                a[mb][3] = odd ? u3 : u2;   // P[g+8,  k0+tg+4]
            }
#pragma unroll
            for (int nt = 0; nt < 8; nt++) {
                uint32_t b0 = Vb[(k0 + tg) * VS_ST + nt * 8 + g];
                uint32_t b1 = Vb[(k0 + tg + 4) * VS_ST + nt * 8 + g];
                mma8(o[0][nt], a[0][0], a[0][1], a[0][2], a[0][3], b0, b1);
                mma8(o[1][nt], a[1][0], a[1][1], a[1][2], a[1][3], b0, b1);
            }
        }

        // ---- commit prefetched tile to the other buffer ----
        if (j < jmax) {
            uint32_t* Kn = Ks + (b ^ 1) * KBUF;
            uint32_t* Vn = Vs + (b ^ 1) * VBUF;
#pragma unroll
            for (int i = 0; i < 8; i++) {
                uint4 uk = make_uint4(f2tf32(pk[i].x), f2tf32(pk[i].y), f2tf32(pk[i].z), f2tf32(pk[i].w));
                *(uint4*)&Kn[krow * QS_ST + kc + i * 4] = uk;
                uint4 uv = make_uint4(f2tf32(pv[i].x), f2tf32(pv[i].y), f2tf32(pv[i].z), f2tf32(pv[i].w));
                *(uint4*)&Vn[krow * VS_ST + kc + i * 4] = uv;
            }
        }
        __syncthreads();   // single barrier per KV tile
    }

    // ---- normalize + store ----
#pragma unroll
    for (int mb = 0; mb < 2; mb++) {
        const float i0 = 1.0f / l_[2 * mb], i1 = 1.0f / l_[2 * mb + 1];
        const int r0 = qt * 128 + wm + mb * 16 + g, r1 = r0 + 8;
#pragma unroll
        for (int nt = 0; nt < 8; nt++) {
            const int c = h * HD + nt * 8 + tg * 2;
            *(float2*)&O[(size_t)r0 * DM + c] = make_float2(o[mb][nt][0] * i0, o[mb][nt][1] * i0);
            *(float2*)&O[(size_t)r1 * DM + c] = make_float2(o[mb][nt][2] * i1, o[mb][nt][3] * i1);
        }
    }
}

// ================= launch =================
extern "C" void kernel_launch(void* const* d_in, const int* in_sizes, int n_in,
                              void* d_out, int out_size)
{
    (void)in_sizes; (void)n_in; (void)out_size;
    const float* x  = (const float*)d_in[0];
    const float* Wq = (const float*)d_in[1];
    const float* Wk = (const float*)d_in[2];
    const float* Wv = (const float*)d_in[3];
    const float* Wp = (const float*)d_in[4];
    float* out = (float*)d_out;

    float *Q, *K, *V, *att;
    cudaGetSymbolAddress((void**)&Q,   g_Q);
    cudaGetSymbolAddress((void**)&K,   g_K);
    cudaGetSymbolAddress((void**)&V,   g_V);
    cudaGetSymbolAddress((void**)&att, g_att);

    const int flash_smem = FLASH_SMEM_WORDS * (int)sizeof(uint32_t);  // 106496 B
    cudaFuncSetAttribute(flash_tc, cudaFuncAttributeMaxDynamicSharedMemorySize, flash_smem);
    cudaFuncSetAttribute(gemm_tc, cudaFuncAttributeMaxDynamicSharedMemorySize, GEMM_SMEM_BYTES);

    // fused QKV projection
    dim3 gq(DM / 128, SEQ / 128, 3);
    gemm_tc<<<gq, 256, GEMM_SMEM_BYTES>>>(x, Wq, Wk, Wv, Q, K, V, SEQ, DM, DM);

    // causal flash attention
    dim3 gf(SEQ / 128, NH);
    flash_tc<<<gf, 128, flash_smem>>>(Q, K, V, att);

    // output projection
    dim3 gp(DM / 128, SEQ / 128, 1);
    gemm_tc<<<gp, 256, GEMM_SMEM_BYTES>>>(att, Wp, Wp, Wp, out, out, out, SEQ, DM, DM);
}

// round 7
// speedup vs baseline: 1.0883x; 1.0883x over previous
#include <cuda_runtime.h>
#include <cuda_fp16.h>
#include <cstdint>

#define SEQ 4096
#define DM  768
#define NH  12
#define HD  64

// ---------------- scratch (no allocations allowed) ----------------
__device__ float  g_Q[SEQ * DM];
__device__ float  g_K[SEQ * DM];
__device__ float  g_V[SEQ * DM];
__device__ float  g_att[SEQ * DM];
__device__ __half g_Vt[DM * SEQ];   // V transposed, fp16: [d_global][s]

// ---------------- helpers ----------------
__device__ __forceinline__ uint32_t f2h2(float lo, float hi) {
    uint32_t r;
    asm("cvt.rn.f16x2.f32 %0, %2, %1;" : "=r"(r) : "f"(lo), "f"(hi));  // low<-lo, high<-hi
    return r;
}
__device__ __forceinline__ float fexp2(float x) {
    float y;
    asm("ex2.approx.ftz.f32 %0, %1;" : "=f"(y) : "f"(x));
    return y;
}
// D += A*B  (m16n8k16 fp16, fp32 accumulate)
__device__ __forceinline__ void mma16(float* d,
                                      uint32_t a0, uint32_t a1, uint32_t a2, uint32_t a3,
                                      uint32_t b0, uint32_t b1) {
    asm volatile(
        "mma.sync.aligned.m16n8k16.row.col.f32.f16.f16.f32 "
        "{%0,%1,%2,%3}, {%4,%5,%6,%7}, {%8,%9}, {%0,%1,%2,%3};"
        : "+f"(d[0]), "+f"(d[1]), "+f"(d[2]), "+f"(d[3])
        : "r"(a0), "r"(a1), "r"(a2), "r"(a3), "r"(b0), "r"(b1));
}

// ================= GEMM: C[M,N] = A[M,K] * B[N,K]^T  (fp16 mma.sync) =================
// 128x128x32 tile, 8 warps, warp tile 64x32. Smem = half2 words, stride 20 (20g+tg bijective mod 32).
#define GS2 20

__global__ __launch_bounds__(256, 2)
void gemm_tc(const float* __restrict__ A,
             const float* __restrict__ B0, const float* __restrict__ B1, const float* __restrict__ B2,
             float* __restrict__ C0, float* __restrict__ C1, float* __restrict__ C2,
             int M, int N, int K)
{
    const float* B = (blockIdx.z == 0) ? B0 : ((blockIdx.z == 1) ? B1 : B2);
    float*       C = (blockIdx.z == 0) ? C0 : ((blockIdx.z == 1) ? C1 : C2);

    __shared__ uint32_t As[128 * GS2];
    __shared__ uint32_t Bs[128 * GS2];

    const int tid  = threadIdx.x;
    const int wid  = tid >> 5;
    const int lane = tid & 31;
    const int g    = lane >> 2;
    const int tg   = lane & 3;
    const int wm   = (wid >> 2) * 64;
    const int wn   = (wid & 3) * 32;
    const int m0   = blockIdx.y * 128;
    const int n0   = blockIdx.x * 128;

    // loader: 2 threads per row, 16 floats each -> 8 half2 words
    const int lrow = tid >> 1;
    const int lc   = (tid & 1) * 16;            // float offset
    const int lw   = lrow * GS2 + (tid & 1) * 8; // word offset in smem

    const float* Ap = A + (size_t)(m0 + lrow) * K + lc;
    const float* Bp = B + (size_t)(n0 + lrow) * K + lc;

    float4 pa[4], pb[4];
#pragma unroll
    for (int i = 0; i < 4; i++) {
        pa[i] = *(const float4*)(Ap + i * 4);
        pb[i] = *(const float4*)(Bp + i * 4);
    }

    float acc[4][4][4] = {};
    const int T = K / 32;

    for (int t = 0; t < T; t++) {
#pragma unroll
        for (int i = 0; i < 2; i++) {
            uint4 wa = make_uint4(f2h2(pa[2*i].x, pa[2*i].y),   f2h2(pa[2*i].z, pa[2*i].w),
                                  f2h2(pa[2*i+1].x, pa[2*i+1].y), f2h2(pa[2*i+1].z, pa[2*i+1].w));
            *(uint4*)&As[lw + i * 4] = wa;
            uint4 wb = make_uint4(f2h2(pb[2*i].x, pb[2*i].y),   f2h2(pb[2*i].z, pb[2*i].w),
                                  f2h2(pb[2*i+1].x, pb[2*i+1].y), f2h2(pb[2*i+1].z, pb[2*i+1].w));
            *(uint4*)&Bs[lw + i * 4] = wb;
        }
        __syncthreads();

        if (t + 1 < T) {
#pragma unroll
            for (int i = 0; i < 4; i++) {
                pa[i] = *(const float4*)(Ap + (t + 1) * 32 + i * 4);
                pb[i] = *(const float4*)(Bp + (t + 1) * 32 + i * 4);
            }
        }

#pragma unroll
        for (int ks = 0; ks < 2; ks++) {        // two k16 chunks cover 32 halves
            const int k0 = ks * 8;              // word offset
            uint32_t af[4][4];
#pragma unroll
            for (int mt = 0; mt < 4; mt++) {
                const int r = wm + mt * 16 + g;
                af[mt][0] = As[r * GS2 + k0 + tg];
                af[mt][1] = As[(r + 8) * GS2 + k0 + tg];
                af[mt][2] = As[r * GS2 + k0 + tg + 4];
                af[mt][3] = As[(r + 8) * GS2 + k0 + tg + 4];
            }
#pragma unroll
            for (int nt = 0; nt < 4; nt++) {
                const int rn = wn + nt * 8 + g;
                uint32_t b0 = Bs[rn * GS2 + k0 + tg];
                uint32_t b1 = Bs[rn * GS2 + k0 + tg + 4];
#pragma unroll
                for (int mt = 0; mt < 4; mt++)
                    mma16(acc[mt][nt], af[mt][0], af[mt][1], af[mt][2], af[mt][3], b0, b1);
            }
        }
        __syncthreads();
    }

#pragma unroll
    for (int mt = 0; mt < 4; mt++) {
        const int r0 = m0 + wm + mt * 16 + g;
#pragma unroll
        for (int nt = 0; nt < 4; nt++) {
            const int c = n0 + wn + nt * 8 + tg * 2;
            *(float2*)&C[(size_t)r0 * N + c]       = make_float2(acc[mt][nt][0], acc[mt][nt][1]);
            *(float2*)&C[(size_t)(r0 + 8) * N + c] = make_float2(acc[mt][nt][2], acc[mt][nt][3]);
        }
    }
}

// ================= V transpose: g_V fp32 [S][D] -> g_Vt fp16 [D][S] =================
__global__ __launch_bounds__(256)
void transpose_v(const float* __restrict__ V, __half* __restrict__ Vt)
{
    __shared__ float t[32][33];
    const int bx = blockIdx.x * 32;   // d
    const int by = blockIdx.y * 32;   // s
    const int tx = threadIdx.x & 31;
    const int ty = threadIdx.x >> 5;  // 0..7
#pragma unroll
    for (int i = 0; i < 32; i += 8)
        t[ty + i][tx] = V[(size_t)(by + ty + i) * DM + bx + tx];
    __syncthreads();
#pragma unroll
    for (int i = 0; i < 32; i += 8)
        Vt[(size_t)(bx + ty + i) * SEQ + by + tx] = __float2half_rn(t[tx][ty + i]);
}

// ================= Flash attention (fp16 m16n8k16, R5 skeleton) =================
// 128-row q-tile, 4 warps x 32 rows, 128 threads, 2 CTAs/SM.
// All smem tiles half2 words, stride 36 (4g+tg bijective mod 32).
#define FS 36
#define SM_Q  0
#define SM_K  (128 * FS)            // 4608
#define SM_V  (SM_K + 64 * FS)      // 6912
#define SM_P  (SM_V + 64 * FS)      // 9216
#define FLASH_SMEM_WORDS (SM_P + 128 * FS)   // 13824 words = 55296 B

__global__ __launch_bounds__(128, 2)
void flash_tc(const float* __restrict__ Qg, const float* __restrict__ Kg,
              const __half* __restrict__ Vt, float* __restrict__ O)
{
    extern __shared__ uint32_t sm[];
    uint32_t* Qs = sm + SM_Q;
    uint32_t* Ks = sm + SM_K;
    uint32_t* Vs = sm + SM_V;
    uint32_t* Ps = sm + SM_P;

    const int qt   = (int)gridDim.x - 1 - blockIdx.x;  // longest blocks first
    const int h    = blockIdx.y;
    const int tid  = threadIdx.x;
    const int lane = tid & 31;
    const int g    = lane >> 2;
    const int tg   = lane & 3;
    const int wm   = (tid >> 5) * 32;   // 4 warps x 32 rows

    // ---- load Q tile (1 row per thread), pre-scaled, fp16 ----
    const float sc = 0.125f * 1.4426950408889634f;
    {
        const float* qp = Qg + (size_t)(qt * 128 + tid) * DM + h * HD;
#pragma unroll
        for (int i = 0; i < 8; i++) {
            float4 v0 = *(const float4*)(qp + i * 8);
            float4 v1 = *(const float4*)(qp + i * 8 + 4);
            uint4 u = make_uint4(f2h2(v0.x * sc, v0.y * sc), f2h2(v0.z * sc, v0.w * sc),
                                 f2h2(v1.x * sc, v1.y * sc), f2h2(v1.z * sc, v1.w * sc));
            *(uint4*)&Qs[tid * FS + i * 4] = u;
        }
    }

    // ---- loader mappings ----
    const int krow = tid >> 1;          // 0..63
    const int kcf  = (tid & 1) * 32;    // float offset into K row
    const int kww  = (tid & 1) * 16;    // word offset into smem row
    const __half* vrow = Vt + (size_t)(h * HD + krow) * SEQ + kcf;  // V^T: row = head-dim

    float4 pk[8];
    uint4  pvt[4];
    {
        const float* kp = Kg + (size_t)krow * DM + h * HD + kcf;    // K tile 0
#pragma unroll
        for (int i = 0; i < 8; i++) pk[i] = *(const float4*)(kp + i * 4);
#pragma unroll
        for (int i = 0; i < 4; i++) pvt[i] = *(const uint4*)(vrow + i * 8);
    }

    float o[2][8][4] = {};
    float m_[4], l_[4];
#pragma unroll
    for (int i = 0; i < 4; i++) { m_[i] = -1e30f; l_[i] = 0.0f; }

    const int jmax = 2 * qt + 1;

    for (int j = 0; j <= jmax; j++) {
        // ---- commit prefetched K tile (fp16) ----
#pragma unroll
        for (int i = 0; i < 2; i++) {
            uint4 uk = make_uint4(f2h2(pk[4*i].x, pk[4*i].y),     f2h2(pk[4*i].z, pk[4*i].w),
                                  f2h2(pk[4*i+1].x, pk[4*i+1].y), f2h2(pk[4*i+1].z, pk[4*i+1].w));
            *(uint4*)&Ks[krow * FS + kww + i * 8] = uk;
            uint4 uk2 = make_uint4(f2h2(pk[4*i+2].x, pk[4*i+2].y), f2h2(pk[4*i+2].z, pk[4*i+2].w),
                                   f2h2(pk[4*i+3].x, pk[4*i+3].y), f2h2(pk[4*i+3].z, pk[4*i+3].w));
            *(uint4*)&Ks[krow * FS + kww + i * 8 + 4] = uk2;
        }
        __syncthreads();   // sync A: Ks ready; prior PV done -> Vs writable

        // ---- prefetch V tile j (already fp16; hidden behind S+softmax) ----
        uint4 pv[4];
#pragma unroll
        for (int i = 0; i < 4; i++) pv[i] = pvt[i];   // pvt holds tile j (loaded last iter or init)

        // ---- S = Q K^T (4 k16 chunks) ----
        float sv[2][8][4] = {};
#pragma unroll
        for (int ck = 0; ck < 4; ck++) {
            const int k0 = ck * 8;
            uint32_t a[2][4];
#pragma unroll
            for (int mb = 0; mb < 2; mb++) {
                const int r = wm + mb * 16 + g;
                a[mb][0] = Qs[r * FS + k0 + tg];
                a[mb][1] = Qs[(r + 8) * FS + k0 + tg];
                a[mb][2] = Qs[r * FS + k0 + tg + 4];
                a[mb][3] = Qs[(r + 8) * FS + k0 + tg + 4];
            }
#pragma unroll
            for (int nt = 0; nt < 8; nt++) {
                uint32_t b0 = Ks[(nt * 8 + g) * FS + k0 + tg];
                uint32_t b1 = Ks[(nt * 8 + g) * FS + k0 + tg + 4];
                mma16(sv[0][nt], a[0][0], a[0][1], a[0][2], a[0][3], b0, b1);
                mma16(sv[1][nt], a[1][0], a[1][1], a[1][2], a[1][3], b0, b1);
            }
        }

        // ---- causal mask ----
        if (j >= 2 * qt) {
            const int cb = j * 64;
#pragma unroll
            for (int mb = 0; mb < 2; mb++) {
                const int r0 = qt * 128 + wm + mb * 16 + g, r1 = r0 + 8;
#pragma unroll
                for (int nt = 0; nt < 8; nt++) {
#pragma unroll
                    for (int cc = 0; cc < 2; cc++) {
                        const int col = cb + nt * 8 + tg * 2 + cc;
                        if (col > r0) sv[mb][nt][cc]     = -1e30f;
                        if (col > r1) sv[mb][nt][2 + cc] = -1e30f;
                    }
                }
            }
        }

        // ---- online softmax (base-2) ----
#pragma unroll
        for (int mb = 0; mb < 2; mb++) {
            float mx0 = -1e30f, mx1 = -1e30f;
#pragma unroll
            for (int nt = 0; nt < 8; nt++) {
                mx0 = fmaxf(mx0, fmaxf(sv[mb][nt][0], sv[mb][nt][1]));
                mx1 = fmaxf(mx1, fmaxf(sv[mb][nt][2], sv[mb][nt][3]));
            }
            mx0 = fmaxf(mx0, __shfl_xor_sync(0xffffffffu, mx0, 1));
            mx0 = fmaxf(mx0, __shfl_xor_sync(0xffffffffu, mx0, 2));
            mx1 = fmaxf(mx1, __shfl_xor_sync(0xffffffffu, mx1, 1));
            mx1 = fmaxf(mx1, __shfl_xor_sync(0xffffffffu, mx1, 2));

            const int g0 = 2 * mb, g1 = 2 * mb + 1;
            const float mn0 = fmaxf(m_[g0], mx0), mn1 = fmaxf(m_[g1], mx1);
            const float al0 = fexp2(m_[g0] - mn0), al1 = fexp2(m_[g1] - mn1);
            float s0 = 0.0f, s1 = 0.0f;
#pragma unroll
            for (int nt = 0; nt < 8; nt++) {
                sv[mb][nt][0] = fexp2(sv[mb][nt][0] - mn0); s0 += sv[mb][nt][0];
                sv[mb][nt][1] = fexp2(sv[mb][nt][1] - mn0); s0 += sv[mb][nt][1];
                sv[mb][nt][2] = fexp2(sv[mb][nt][2] - mn1); s1 += sv[mb][nt][2];
                sv[mb][nt][3] = fexp2(sv[mb][nt][3] - mn1); s1 += sv[mb][nt][3];
            }
            s0 += __shfl_xor_sync(0xffffffffu, s0, 1);
            s0 += __shfl_xor_sync(0xffffffffu, s0, 2);
            s1 += __shfl_xor_sync(0xffffffffu, s1, 1);
            s1 += __shfl_xor_sync(0xffffffffu, s1, 2);
            l_[g0] = l_[g0] * al0 + s0;  l_[g1] = l_[g1] * al1 + s1;
            m_[g0] = mn0;  m_[g1] = mn1;
#pragma unroll
            for (int nt = 0; nt < 8; nt++) {
                o[mb][nt][0] *= al0; o[mb][nt][1] *= al0;
                o[mb][nt][2] *= al1; o[mb][nt][3] *= al1;
            }
        }

        // ---- commit V tile [n][k] (writable since sync A) ----
#pragma unroll
        for (int i = 0; i < 4; i++)
            *(uint4*)&Vs[krow * FS + kww + i * 4] = pv[i];

        // ---- P to smem: one half2 word per (row-half, nt) ----
#pragma unroll
        for (int mb = 0; mb < 2; mb++) {
            const int r = wm + mb * 16 + g;
#pragma unroll
            for (int nt = 0; nt < 8; nt++) {
                Ps[r * FS + nt * 4 + tg]       = f2h2(sv[mb][nt][0], sv[mb][nt][1]);
                Ps[(r + 8) * FS + nt * 4 + tg] = f2h2(sv[mb][nt][2], sv[mb][nt][3]);
            }
        }

        // ---- prefetch K/V tile j+1 (hidden behind PV) ----
        if (j < jmax) {
            const float* kp = Kg + (size_t)((j + 1) * 64 + krow) * DM + h * HD + kcf;
#pragma unroll
            for (int i = 0; i < 8; i++) pk[i] = *(const float4*)(kp + i * 4);
            const __half* vp = vrow + (size_t)(j + 1) * 64;
#pragma unroll
            for (int i = 0; i < 4; i++) pvt[i] = *(const uint4*)(vp + i * 8);
        }
        __syncthreads();   // sync B: Vs ready; own P visible to own warp

        // ---- O += P V  (4 k16 chunks over 64 KV positions) ----
#pragma unroll
        for (int ck = 0; ck < 4; ck++) {
            const int k0 = ck * 8;
            uint32_t a[2][4];
#pragma unroll
            for (int mb = 0; mb < 2; mb++) {
                const int r = wm + mb * 16 + g;
                a[mb][0] = Ps[r * FS + k0 + tg];
                a[mb][1] = Ps[(r + 8) * FS + k0 + tg];
                a[mb][2] = Ps[r * FS + k0 + tg + 4];
                a[mb][3] = Ps[(r + 8) * FS + k0 + tg + 4];
            }
#pragma unroll
            for (int nt = 0; nt < 8; nt++) {
                uint32_t b0 = Vs[(nt * 8 + g) * FS + k0 + tg];
                uint32_t b1 = Vs[(nt * 8 + g) * FS + k0 + tg + 4];
                mma16(o[0][nt], a[0][0], a[0][1], a[0][2], a[0][3], b0, b1);
                mma16(o[1][nt], a[1][0], a[1][1], a[1][2], a[1][3], b0, b1);
            }
        }
        // no trailing sync: Ks rewrite races nothing (readers done before sync B);
        // Vs rewrite of j+1 happens after its sync A, which orders all PV reads of j.
    }

    // ---- normalize + store ----
#pragma unroll
    for (int mb = 0; mb < 2; mb++) {
        const float i0 = 1.0f / l_[2 * mb], i1 = 1.0f / l_[2 * mb + 1];
        const int r0 = qt * 128 + wm + mb * 16 + g, r1 = r0 + 8;
#pragma unroll
        for (int nt = 0; nt < 8; nt++) {
            const int c = h * HD + nt * 8 + tg * 2;
            *(float2*)&O[(size_t)r0 * DM + c] = make_float2(o[mb][nt][0] * i0, o[mb][nt][1] * i0);
            *(float2*)&O[(size_t)r1 * DM + c] = make_float2(o[mb][nt][2] * i1, o[mb][nt][3] * i1);
        }
    }
}

// ================= launch =================
extern "C" void kernel_launch(void* const* d_in, const int* in_sizes, int n_in,
                              void* d_out, int out_size)
{
    (void)in_sizes; (void)n_in; (void)out_size;
    const float* x  = (const float*)d_in[0];
    const float* Wq = (const float*)d_in[1];
    const float* Wk = (const float*)d_in[2];
    const float* Wv = (const float*)d_in[3];
    const float* Wp = (const float*)d_in[4];
    float* out = (float*)d_out;

    float *Q, *K, *V, *att;
    __half* Vt;
    cudaGetSymbolAddress((void**)&Q,   g_Q);
    cudaGetSymbolAddress((void**)&K,   g_K);
    cudaGetSymbolAddress((void**)&V,   g_V);
    cudaGetSymbolAddress((void**)&att, g_att);
    cudaGetSymbolAddress((void**)&Vt,  g_Vt);

    const int flash_smem = FLASH_SMEM_WORDS * (int)sizeof(uint32_t);  // 55296 B
    cudaFuncSetAttribute(flash_tc, cudaFuncAttributeMaxDynamicSharedMemorySize, flash_smem);

    // fused QKV projection (fp16 tensor cores)
    dim3 gq(DM / 128, SEQ / 128, 3);
    gemm_tc<<<gq, 256>>>(x, Wq, Wk, Wv, Q, K, V, SEQ, DM, DM);

    // transpose V -> fp16 [D][S]
    dim3 gt(DM / 32, SEQ / 32);
    transpose_v<<<gt, 256>>>(V, Vt);

    // causal flash attention
    dim3 gf(SEQ / 128, NH);
    flash_tc<<<gf, 128, flash_smem>>>(Q, K, Vt, att);

    // output projection
    dim3 gp(DM / 128, SEQ / 128, 1);
    gemm_tc<<<gp, 256>>>(att, Wp, Wp, Wp, out, out, out, SEQ, DM, DM);
}

// round 8
// speedup vs baseline: 1.6890x; 1.5520x over previous
#include <cuda_runtime.h>
#include <cuda_fp16.h>
#include <cstdint>

#define SEQ 4096
#define DM  768
#define NH  12
#define HD  64

// ---------------- scratch (no allocations allowed) ----------------
__device__ float  g_Q[SEQ * DM];
__device__ float  g_K[SEQ * DM];
__device__ float  g_V[SEQ * DM];
__device__ float  g_att[SEQ * DM];
__device__ __half g_Vt[DM * SEQ];   // V transposed, fp16: [d_global][s]
__device__ int    g_unit_ctr;       // flash work-queue counter (reset by transpose_v)

// ---------------- helpers ----------------
__device__ __forceinline__ uint32_t f2h2(float lo, float hi) {
    uint32_t r;
    asm("cvt.rn.f16x2.f32 %0, %2, %1;" : "=r"(r) : "f"(lo), "f"(hi));  // low<-lo, high<-hi
    return r;
}
__device__ __forceinline__ float fexp2(float x) {
    float y;
    asm("ex2.approx.ftz.f32 %0, %1;" : "=f"(y) : "f"(x));
    return y;
}
// D += A*B  (m16n8k16 fp16, fp32 accumulate)
__device__ __forceinline__ void mma16(float* d,
                                      uint32_t a0, uint32_t a1, uint32_t a2, uint32_t a3,
                                      uint32_t b0, uint32_t b1) {
    asm volatile(
        "mma.sync.aligned.m16n8k16.row.col.f32.f16.f16.f32 "
        "{%0,%1,%2,%3}, {%4,%5,%6,%7}, {%8,%9}, {%0,%1,%2,%3};"
        : "+f"(d[0]), "+f"(d[1]), "+f"(d[2]), "+f"(d[3])
        : "r"(a0), "r"(a1), "r"(a2), "r"(a3), "r"(b0), "r"(b1));
}

// ================= GEMM: C[M,N] = A[M,K] * B[N,K]^T  (fp16, double-buffered) =================
// 128x128x32 tile, 8 warps, warp tile 64x32. half2 smem stride 20; ONE sync per k-tile.
#define GS2 20
#define GW  (128 * GS2)   // 2560 words per operand buffer

__global__ __launch_bounds__(256, 2)
void gemm_tc(const float* __restrict__ A,
             const float* __restrict__ B0, const float* __restrict__ B1, const float* __restrict__ B2,
             float* __restrict__ C0, float* __restrict__ C1, float* __restrict__ C2,
             int M, int N, int K)
{
    const float* B = (blockIdx.z == 0) ? B0 : ((blockIdx.z == 1) ? B1 : B2);
    float*       C = (blockIdx.z == 0) ? C0 : ((blockIdx.z == 1) ? C1 : C2);

    __shared__ uint32_t As[2 * GW];
    __shared__ uint32_t Bs[2 * GW];

    const int tid  = threadIdx.x;
    const int wid  = tid >> 5;
    const int lane = tid & 31;
    const int g    = lane >> 2;
    const int tg   = lane & 3;
    const int wm   = (wid >> 2) * 64;
    const int wn   = (wid & 3) * 32;
    const int m0   = blockIdx.y * 128;
    const int n0   = blockIdx.x * 128;

    // loader: 2 threads per row, 16 floats each -> 8 half2 words
    const int lrow = tid >> 1;
    const int lc   = (tid & 1) * 16;             // float offset
    const int lw   = lrow * GS2 + (tid & 1) * 8; // word offset in smem

    const float* Ap = A + (size_t)(m0 + lrow) * K + lc;
    const float* Bp = B + (size_t)(n0 + lrow) * K + lc;

    float4 pa[4], pb[4];
#pragma unroll
    for (int i = 0; i < 4; i++) {
        pa[i] = *(const float4*)(Ap + i * 4);
        pb[i] = *(const float4*)(Bp + i * 4);
    }
    // commit tile 0 into buffer 0
#pragma unroll
    for (int i = 0; i < 2; i++) {
        uint4 wa = make_uint4(f2h2(pa[2*i].x, pa[2*i].y),     f2h2(pa[2*i].z, pa[2*i].w),
                              f2h2(pa[2*i+1].x, pa[2*i+1].y), f2h2(pa[2*i+1].z, pa[2*i+1].w));
        *(uint4*)&As[lw + i * 4] = wa;
        uint4 wb = make_uint4(f2h2(pb[2*i].x, pb[2*i].y),     f2h2(pb[2*i].z, pb[2*i].w),
                              f2h2(pb[2*i+1].x, pb[2*i+1].y), f2h2(pb[2*i+1].z, pb[2*i+1].w));
        *(uint4*)&Bs[lw + i * 4] = wb;
    }
    __syncthreads();

    float acc[4][4][4] = {};
    const int T = K / 32;

    for (int t = 0; t < T; t++) {
        const int b = t & 1;
        const uint32_t* Ab = As + b * GW;
        const uint32_t* Bb = Bs + b * GW;

        if (t + 1 < T) {
#pragma unroll
            for (int i = 0; i < 4; i++) {
                pa[i] = *(const float4*)(Ap + (t + 1) * 32 + i * 4);
                pb[i] = *(const float4*)(Bp + (t + 1) * 32 + i * 4);
            }
        }

#pragma unroll
        for (int ks = 0; ks < 2; ks++) {
            const int k0 = ks * 8;
            uint32_t af[4][4];
#pragma unroll
            for (int mt = 0; mt < 4; mt++) {
                const int r = wm + mt * 16 + g;
                af[mt][0] = Ab[r * GS2 + k0 + tg];
                af[mt][1] = Ab[(r + 8) * GS2 + k0 + tg];
                af[mt][2] = Ab[r * GS2 + k0 + tg + 4];
                af[mt][3] = Ab[(r + 8) * GS2 + k0 + tg + 4];
            }
#pragma unroll
            for (int nt = 0; nt < 4; nt++) {
                const int rn = wn + nt * 8 + g;
                uint32_t b0 = Bb[rn * GS2 + k0 + tg];
                uint32_t b1 = Bb[rn * GS2 + k0 + tg + 4];
#pragma unroll
                for (int mt = 0; mt < 4; mt++)
                    mma16(acc[mt][nt], af[mt][0], af[mt][1], af[mt][2], af[mt][3], b0, b1);
            }
        }

        if (t + 1 < T) {
            uint32_t* An = As + (b ^ 1) * GW;
            uint32_t* Bn = Bs + (b ^ 1) * GW;
#pragma unroll
            for (int i = 0; i < 2; i++) {
                uint4 wa = make_uint4(f2h2(pa[2*i].x, pa[2*i].y),     f2h2(pa[2*i].z, pa[2*i].w),
                                      f2h2(pa[2*i+1].x, pa[2*i+1].y), f2h2(pa[2*i+1].z, pa[2*i+1].w));
                *(uint4*)&An[lw + i * 4] = wa;
                uint4 wb = make_uint4(f2h2(pb[2*i].x, pb[2*i].y),     f2h2(pb[2*i].z, pb[2*i].w),
                                      f2h2(pb[2*i+1].x, pb[2*i+1].y), f2h2(pb[2*i+1].z, pb[2*i+1].w));
                *(uint4*)&Bn[lw + i * 4] = wb;
            }
        }
        __syncthreads();
    }

#pragma unroll
    for (int mt = 0; mt < 4; mt++) {
        const int r0 = m0 + wm + mt * 16 + g;
#pragma unroll
        for (int nt = 0; nt < 4; nt++) {
            const int c = n0 + wn + nt * 8 + tg * 2;
            *(float2*)&C[(size_t)r0 * N + c]       = make_float2(acc[mt][nt][0], acc[mt][nt][1]);
            *(float2*)&C[(size_t)(r0 + 8) * N + c] = make_float2(acc[mt][nt][2], acc[mt][nt][3]);
        }
    }
}

// ================= V transpose + queue reset =================
__global__ __launch_bounds__(256)
void transpose_v(const float* __restrict__ V, __half* __restrict__ Vt)
{
    if (blockIdx.x == 0 && blockIdx.y == 0 && threadIdx.x == 0)
        g_unit_ctr = 0;   // reset flash work queue every replay (stream-ordered before flash)

    __shared__ float t[32][33];
    const int bx = blockIdx.x * 32;   // d
    const int by = blockIdx.y * 32;   // s
    const int tx = threadIdx.x & 31;
    const int ty = threadIdx.x >> 5;  // 0..7
#pragma unroll
    for (int i = 0; i < 32; i += 8)
        t[ty + i][tx] = V[(size_t)(by + ty + i) * DM + bx + tx];
    __syncthreads();
#pragma unroll
    for (int i = 0; i < 32; i += 8)
        Vt[(size_t)(bx + ty + i) * SEQ + by + tx] = __float2half_rn(t[tx][ty + i]);
}

// ================= Flash attention (fp16, persistent work-queue) =================
// 128-row q-tile, 4 warps x 32 rows, 128 threads, 2 CTAs/SM, 296 persistent CTAs.
// Units (head, qt) dispensed longest-first via atomicAdd -> LPT load balance.
#define FS 36
#define SM_Q  0
#define SM_K  (128 * FS)            // 4608
#define SM_V  (SM_K + 64 * FS)      // 6912
#define SM_P  (SM_V + 64 * FS)      // 9216
#define FLASH_SMEM_WORDS (SM_P + 128 * FS)   // 13824 words = 55296 B
#define N_UNITS (32 * NH)           // 384
#define FLASH_GRID 296

__global__ __launch_bounds__(128, 2)
void flash_tc(const float* __restrict__ Qg, const float* __restrict__ Kg,
              const __half* __restrict__ Vt, float* __restrict__ O)
{
    extern __shared__ uint32_t sm[];
    __shared__ int s_unit;
    uint32_t* Qs = sm + SM_Q;
    uint32_t* Ks = sm + SM_K;
    uint32_t* Vs = sm + SM_V;
    uint32_t* Ps = sm + SM_P;

    const int tid  = threadIdx.x;
    const int lane = tid & 31;
    const int g    = lane >> 2;
    const int tg   = lane & 3;
    const int wm   = (tid >> 5) * 32;   // 4 warps x 32 rows

    const int krow = tid >> 1;          // 0..63
    const int kcf  = (tid & 1) * 32;    // float offset into K row
    const int kww  = (tid & 1) * 16;    // word offset into smem row
    const float sc = 0.125f * 1.4426950408889634f;

    for (;;) {
        if (tid == 0) s_unit = atomicAdd(&g_unit_ctr, 1);
        __syncthreads();                 // publishes s_unit; also fences prior unit's smem use
        const int u = s_unit;
        if (u >= N_UNITS) return;
        const int qt = 31 - u / NH;      // longest-first
        const int h  = u % NH;

        // ---- load Q tile (1 row per thread), pre-scaled, fp16 ----
        {
            const float* qp = Qg + (size_t)(qt * 128 + tid) * DM + h * HD;
#pragma unroll
            for (int i = 0; i < 8; i++) {
                float4 v0 = *(const float4*)(qp + i * 8);
                float4 v1 = *(const float4*)(qp + i * 8 + 4);
                uint4 uq = make_uint4(f2h2(v0.x * sc, v0.y * sc), f2h2(v0.z * sc, v0.w * sc),
                                      f2h2(v1.x * sc, v1.y * sc), f2h2(v1.z * sc, v1.w * sc));
                *(uint4*)&Qs[tid * FS + i * 4] = uq;
            }
        }

        const __half* vrow = Vt + (size_t)(h * HD + krow) * SEQ + kcf;

        float4 pk[8];
        uint4  pvt[4];
        {
            const float* kp = Kg + (size_t)krow * DM + h * HD + kcf;    // K tile 0
#pragma unroll
            for (int i = 0; i < 8; i++) pk[i] = *(const float4*)(kp + i * 4);
#pragma unroll
            for (int i = 0; i < 4; i++) pvt[i] = *(const uint4*)(vrow + i * 8);
        }

        float o[2][8][4] = {};
        float m_[4], l_[4];
#pragma unroll
        for (int i = 0; i < 4; i++) { m_[i] = -1e30f; l_[i] = 0.0f; }

        const int jmax = 2 * qt + 1;

        for (int j = 0; j <= jmax; j++) {
            // ---- commit prefetched K tile (fp16) ----
#pragma unroll
            for (int i = 0; i < 2; i++) {
                uint4 uk = make_uint4(f2h2(pk[4*i].x, pk[4*i].y),     f2h2(pk[4*i].z, pk[4*i].w),
                                      f2h2(pk[4*i+1].x, pk[4*i+1].y), f2h2(pk[4*i+1].z, pk[4*i+1].w));
                *(uint4*)&Ks[krow * FS + kww + i * 8] = uk;
                uint4 uk2 = make_uint4(f2h2(pk[4*i+2].x, pk[4*i+2].y), f2h2(pk[4*i+2].z, pk[4*i+2].w),
                                       f2h2(pk[4*i+3].x, pk[4*i+3].y), f2h2(pk[4*i+3].z, pk[4*i+3].w));
                *(uint4*)&Ks[krow * FS + kww + i * 8 + 4] = uk2;
            }
            __syncthreads();   // sync A: Ks ready; prior PV done -> Vs writable

            uint4 pv[4];
#pragma unroll
            for (int i = 0; i < 4; i++) pv[i] = pvt[i];   // V tile j (fp16, loaded earlier)

            // ---- S = Q K^T (4 k16 chunks) ----
            float sv[2][8][4] = {};
#pragma unroll
            for (int ck = 0; ck < 4; ck++) {
                const int k0 = ck * 8;
                uint32_t a[2][4];
#pragma unroll
                for (int mb = 0; mb < 2; mb++) {
                    const int r = wm + mb * 16 + g;
                    a[mb][0] = Qs[r * FS + k0 + tg];
                    a[mb][1] = Qs[(r + 8) * FS + k0 + tg];
                    a[mb][2] = Qs[r * FS + k0 + tg + 4];
                    a[mb][3] = Qs[(r + 8) * FS + k0 + tg + 4];
                }
#pragma unroll
                for (int nt = 0; nt < 8; nt++) {
                    uint32_t b0 = Ks[(nt * 8 + g) * FS + k0 + tg];
                    uint32_t b1 = Ks[(nt * 8 + g) * FS + k0 + tg + 4];
                    mma16(sv[0][nt], a[0][0], a[0][1], a[0][2], a[0][3], b0, b1);
                    mma16(sv[1][nt], a[1][0], a[1][1], a[1][2], a[1][3], b0, b1);
                }
            }

            // ---- causal mask ----
            if (j >= 2 * qt) {
                const int cb = j * 64;
#pragma unroll
                for (int mb = 0; mb < 2; mb++) {
                    const int r0 = qt * 128 + wm + mb * 16 + g, r1 = r0 + 8;
#pragma unroll
                    for (int nt = 0; nt < 8; nt++) {
#pragma unroll
                        for (int cc = 0; cc < 2; cc++) {
                            const int col = cb + nt * 8 + tg * 2 + cc;
                            if (col > r0) sv[mb][nt][cc]     = -1e30f;
                            if (col > r1) sv[mb][nt][2 + cc] = -1e30f;
                        }
                    }
                }
            }

            // ---- online softmax (base-2) ----
#pragma unroll
            for (int mb = 0; mb < 2; mb++) {
                float mx0 = -1e30f, mx1 = -1e30f;
#pragma unroll
                for (int nt = 0; nt < 8; nt++) {
                    mx0 = fmaxf(mx0, fmaxf(sv[mb][nt][0], sv[mb][nt][1]));
                    mx1 = fmaxf(mx1, fmaxf(sv[mb][nt][2], sv[mb][nt][3]));
                }
                mx0 = fmaxf(mx0, __shfl_xor_sync(0xffffffffu, mx0, 1));
                mx0 = fmaxf(mx0, __shfl_xor_sync(0xffffffffu, mx0, 2));
                mx1 = fmaxf(mx1, __shfl_xor_sync(0xffffffffu, mx1, 1));
                mx1 = fmaxf(mx1, __shfl_xor_sync(0xffffffffu, mx1, 2));

                const int g0 = 2 * mb, g1 = 2 * mb + 1;
                const float mn0 = fmaxf(m_[g0], mx0), mn1 = fmaxf(m_[g1], mx1);
                const float al0 = fexp2(m_[g0] - mn0), al1 = fexp2(m_[g1] - mn1);
                float s0 = 0.0f, s1 = 0.0f;
#pragma unroll
                for (int nt = 0; nt < 8; nt++) {
                    sv[mb][nt][0] = fexp2(sv[mb][nt][0] - mn0); s0 += sv[mb][nt][0];
                    sv[mb][nt][1] = fexp2(sv[mb][nt][1] - mn0); s0 += sv[mb][nt][1];
                    sv[mb][nt][2] = fexp2(sv[mb][nt][2] - mn1); s1 += sv[mb][nt][2];
                    sv[mb][nt][3] = fexp2(sv[mb][nt][3] - mn1); s1 += sv[mb][nt][3];
                }
                s0 += __shfl_xor_sync(0xffffffffu, s0, 1);
                s0 += __shfl_xor_sync(0xffffffffu, s0, 2);
                s1 += __shfl_xor_sync(0xffffffffu, s1, 1);
                s1 += __shfl_xor_sync(0xffffffffu, s1, 2);
                l_[g0] = l_[g0] * al0 + s0;  l_[g1] = l_[g1] * al1 + s1;
                m_[g0] = mn0;  m_[g1] = mn1;
#pragma unroll
                for (int nt = 0; nt < 8; nt++) {
                    o[mb][nt][0] *= al0; o[mb][nt][1] *= al0;
                    o[mb][nt][2] *= al1; o[mb][nt][3] *= al1;
                }
            }

            // ---- commit V tile [n][k] (writable since sync A) ----
#pragma unroll
            for (int i = 0; i < 4; i++)
                *(uint4*)&Vs[krow * FS + kww + i * 4] = pv[i];

            // ---- P to smem: one half2 word per (row-half, nt) ----
#pragma unroll
            for (int mb = 0; mb < 2; mb++) {
                const int r = wm + mb * 16 + g;
#pragma unroll
                for (int nt = 0; nt < 8; nt++) {
                    Ps[r * FS + nt * 4 + tg]       = f2h2(sv[mb][nt][0], sv[mb][nt][1]);
                    Ps[(r + 8) * FS + nt * 4 + tg] = f2h2(sv[mb][nt][2], sv[mb][nt][3]);
                }
            }

            // ---- prefetch K/V tile j+1 (hidden behind PV) ----
            if (j < jmax) {
                const float* kp = Kg + (size_t)((j + 1) * 64 + krow) * DM + h * HD + kcf;
#pragma unroll
                for (int i = 0; i < 8; i++) pk[i] = *(const float4*)(kp + i * 4);
                const __half* vp = vrow + (size_t)(j + 1) * 64;
#pragma unroll
                for (int i = 0; i < 4; i++) pvt[i] = *(const uint4*)(vp + i * 8);
            }
            __syncthreads();   // sync B: Vs ready; own P visible

            // ---- O += P V ----
#pragma unroll
            for (int ck = 0; ck < 4; ck++) {
                const int k0 = ck * 8;
                uint32_t a[2][4];
#pragma unroll
                for (int mb = 0; mb < 2; mb++) {
                    const int r = wm + mb * 16 + g;
                    a[mb][0] = Ps[r * FS + k0 + tg];
                    a[mb][1] = Ps[(r + 8) * FS + k0 + tg];
                    a[mb][2] = Ps[r * FS + k0 + tg + 4];
                    a[mb][3] = Ps[(r + 8) * FS + k0 + tg + 4];
                }
#pragma unroll
                for (int nt = 0; nt < 8; nt++) {
                    uint32_t b0 = Vs[(nt * 8 + g) * FS + k0 + tg];
                    uint32_t b1 = Vs[(nt * 8 + g) * FS + k0 + tg + 4];
                    mma16(o[0][nt], a[0][0], a[0][1], a[0][2], a[0][3], b0, b1);
                    mma16(o[1][nt], a[1][0], a[1][1], a[1][2], a[1][3], b0, b1);
                }
            }
        }

        // ---- normalize + store ----
#pragma unroll
        for (int mb = 0; mb < 2; mb++) {
            const float i0 = 1.0f / l_[2 * mb], i1 = 1.0f / l_[2 * mb + 1];
            const int r0 = qt * 128 + wm + mb * 16 + g, r1 = r0 + 8;
#pragma unroll
            for (int nt = 0; nt < 8; nt++) {
                const int c = h * HD + nt * 8 + tg * 2;
                *(float2*)&O[(size_t)r0 * DM + c] = make_float2(o[mb][nt][0] * i0, o[mb][nt][1] * i0);
                *(float2*)&O[(size_t)r1 * DM + c] = make_float2(o[mb][nt][2] * i1, o[mb][nt][3] * i1);
            }
        }
        // loop back: top __syncthreads orders next unit's smem writes after this unit's reads
    }
}

// ================= launch =================
extern "C" void kernel_launch(void* const* d_in, const int* in_sizes, int n_in,
                              void* d_out, int out_size)
{
    (void)in_sizes; (void)n_in; (void)out_size;
    const float* x  = (const float*)d_in[0];
    const float* Wq = (const float*)d_in[1];
    const float* Wk = (const float*)d_in[2];
    const float* Wv = (const float*)d_in[3];
    const float* Wp = (const float*)d_in[4];
    float* out = (float*)d_out;

    float *Q, *K, *V, *att;
    __half* Vt;
    cudaGetSymbolAddress((void**)&Q,   g_Q);
    cudaGetSymbolAddress((void**)&K,   g_K);
    cudaGetSymbolAddress((void**)&V,   g_V);
    cudaGetSymbolAddress((void**)&att, g_att);
    cudaGetSymbolAddress((void**)&Vt,  g_Vt);

    const int flash_smem = FLASH_SMEM_WORDS * (int)sizeof(uint32_t);  // 55296 B
    cudaFuncSetAttribute(flash_tc, cudaFuncAttributeMaxDynamicSharedMemorySize, flash_smem);

    // fused QKV projection (fp16, double-buffered)
    dim3 gq(DM / 128, SEQ / 128, 3);
    gemm_tc<<<gq, 256>>>(x, Wq, Wk, Wv, Q, K, V, SEQ, DM, DM);

    // transpose V -> fp16 [D][S]  (also resets the flash work queue)
    dim3 gt(DM / 32, SEQ / 32);
    transpose_v<<<gt, 256>>>(V, Vt);

    // causal flash attention: persistent CTAs + LPT work queue
    flash_tc<<<FLASH_GRID, 128, flash_smem>>>(Q, K, Vt, att);

    // output projection
    dim3 gp(DM / 128, SEQ / 128, 1);
    gemm_tc<<<gp, 256>>>(att, Wp, Wp, Wp, out, out, out, SEQ, DM, DM);
}

// round 9
// speedup vs baseline: 1.9437x; 1.1508x over previous
#include <cuda_runtime.h>
#include <cuda_fp16.h>
#include <cstdint>

#define SEQ 4096
#define DM  768
#define NH  12
#define HD  64

// ---------------- scratch (no allocations allowed) ----------------
__device__ __half g_Qh[SEQ * DM];    // Q fp16, pre-scaled by 0.125*log2e
__device__ __half g_Kh[SEQ * DM];    // K fp16
__device__ __half g_Vh[SEQ * DM];    // V fp16 [s][d]
__device__ __half g_Vt[DM * SEQ];    // V fp16 transposed [d][s]
__device__ __half g_att[SEQ * DM];   // attention output fp16
__device__ int    g_unit_ctr;        // flash work-queue counter (reset by transpose_v)

// ---------------- helpers ----------------
__device__ __forceinline__ uint32_t f2h2(float lo, float hi) {
    uint32_t r;
    asm("cvt.rn.f16x2.f32 %0, %2, %1;" : "=r"(r) : "f"(lo), "f"(hi));  // low<-lo, high<-hi
    return r;
}
__device__ __forceinline__ float fexp2(float x) {
    float y;
    asm("ex2.approx.ftz.f32 %0, %1;" : "=f"(y) : "f"(x));
    return y;
}
__device__ __forceinline__ uint32_t smem_u32(const void* p) {
    uint32_t a;
    asm("{ .reg .u64 t; cvta.to.shared.u64 t, %1; cvt.u32.u64 %0, t; }" : "=r"(a) : "l"(p));
    return a;
}
#define CP_ASYNC16(dst, src) \
    asm volatile("cp.async.ca.shared.global [%0], [%1], 16;" :: "r"(dst), "l"(src) : "memory")
#define CP_COMMIT() asm volatile("cp.async.commit_group;" ::: "memory")
#define CP_WAIT0()  asm volatile("cp.async.wait_group 0;" ::: "memory")

// D += A*B  (m16n8k16 fp16, fp32 accumulate)
__device__ __forceinline__ void mma16(float* d,
                                      uint32_t a0, uint32_t a1, uint32_t a2, uint32_t a3,
                                      uint32_t b0, uint32_t b1) {
    asm volatile(
        "mma.sync.aligned.m16n8k16.row.col.f32.f16.f16.f32 "
        "{%0,%1,%2,%3}, {%4,%5,%6,%7}, {%8,%9}, {%0,%1,%2,%3};"
        : "+f"(d[0]), "+f"(d[1]), "+f"(d[2]), "+f"(d[3])
        : "r"(a0), "r"(a1), "r"(a2), "r"(a3), "r"(b0), "r"(b1));
}

#define QK_SCALE 0.1803368801111204f   // 0.125 * log2(e)

// ================= QKV GEMM: Ch[M,N] = A[M,K] * B[N,K]^T, fp16 out =================
// 128x128x32, 8 warps, double-buffered, 1 sync/k-tile. Q (z==0) scaled by QK_SCALE.
#define GS2 20
#define GW  (128 * GS2)

__global__ __launch_bounds__(256, 2)
void gemm_qkv(const float* __restrict__ A,
              const float* __restrict__ B0, const float* __restrict__ B1, const float* __restrict__ B2,
              __half* __restrict__ C0, __half* __restrict__ C1, __half* __restrict__ C2,
              int M, int N, int K)
{
    const float* B = (blockIdx.z == 0) ? B0 : ((blockIdx.z == 1) ? B1 : B2);
    __half*      C = (blockIdx.z == 0) ? C0 : ((blockIdx.z == 1) ? C1 : C2);
    const float  cs = (blockIdx.z == 0) ? QK_SCALE : 1.0f;

    __shared__ uint32_t As[2 * GW];
    __shared__ uint32_t Bs[2 * GW];

    const int tid  = threadIdx.x;
    const int wid  = tid >> 5;
    const int lane = tid & 31;
    const int g    = lane >> 2;
    const int tg   = lane & 3;
    const int wm   = (wid >> 2) * 64;
    const int wn   = (wid & 3) * 32;
    const int m0   = blockIdx.y * 128;
    const int n0   = blockIdx.x * 128;

    const int lrow = tid >> 1;
    const int lc   = (tid & 1) * 16;
    const int lw   = lrow * GS2 + (tid & 1) * 8;

    const float* Ap = A + (size_t)(m0 + lrow) * K + lc;
    const float* Bp = B + (size_t)(n0 + lrow) * K + lc;

    float4 pa[4], pb[4];
#pragma unroll
    for (int i = 0; i < 4; i++) {
        pa[i] = *(const float4*)(Ap + i * 4);
        pb[i] = *(const float4*)(Bp + i * 4);
    }
#pragma unroll
    for (int i = 0; i < 2; i++) {
        uint4 wa = make_uint4(f2h2(pa[2*i].x, pa[2*i].y),     f2h2(pa[2*i].z, pa[2*i].w),
                              f2h2(pa[2*i+1].x, pa[2*i+1].y), f2h2(pa[2*i+1].z, pa[2*i+1].w));
        *(uint4*)&As[lw + i * 4] = wa;
        uint4 wb = make_uint4(f2h2(pb[2*i].x, pb[2*i].y),     f2h2(pb[2*i].z, pb[2*i].w),
                              f2h2(pb[2*i+1].x, pb[2*i+1].y), f2h2(pb[2*i+1].z, pb[2*i+1].w));
        *(uint4*)&Bs[lw + i * 4] = wb;
    }
    __syncthreads();

    float acc[4][4][4] = {};
    const int T = K / 32;

    for (int t = 0; t < T; t++) {
        const int b = t & 1;
        const uint32_t* Ab = As + b * GW;
        const uint32_t* Bb = Bs + b * GW;

        if (t + 1 < T) {
#pragma unroll
            for (int i = 0; i < 4; i++) {
                pa[i] = *(const float4*)(Ap + (t + 1) * 32 + i * 4);
                pb[i] = *(const float4*)(Bp + (t + 1) * 32 + i * 4);
            }
        }

#pragma unroll
        for (int ks = 0; ks < 2; ks++) {
            const int k0 = ks * 8;
            uint32_t af[4][4];
#pragma unroll
            for (int mt = 0; mt < 4; mt++) {
                const int r = wm + mt * 16 + g;
                af[mt][0] = Ab[r * GS2 + k0 + tg];
                af[mt][1] = Ab[(r + 8) * GS2 + k0 + tg];
                af[mt][2] = Ab[r * GS2 + k0 + tg + 4];
                af[mt][3] = Ab[(r + 8) * GS2 + k0 + tg + 4];
            }
#pragma unroll
            for (int nt = 0; nt < 4; nt++) {
                const int rn = wn + nt * 8 + g;
                uint32_t b0 = Bb[rn * GS2 + k0 + tg];
                uint32_t b1 = Bb[rn * GS2 + k0 + tg + 4];
#pragma unroll
                for (int mt = 0; mt < 4; mt++)
                    mma16(acc[mt][nt], af[mt][0], af[mt][1], af[mt][2], af[mt][3], b0, b1);
            }
        }

        if (t + 1 < T) {
            uint32_t* An = As + (b ^ 1) * GW;
            uint32_t* Bn = Bs + (b ^ 1) * GW;
#pragma unroll
            for (int i = 0; i < 2; i++) {
                uint4 wa = make_uint4(f2h2(pa[2*i].x, pa[2*i].y),     f2h2(pa[2*i].z, pa[2*i].w),
                                      f2h2(pa[2*i+1].x, pa[2*i+1].y), f2h2(pa[2*i+1].z, pa[2*i+1].w));
                *(uint4*)&An[lw + i * 4] = wa;
                uint4 wb = make_uint4(f2h2(pb[2*i].x, pb[2*i].y),     f2h2(pb[2*i].z, pb[2*i].w),
                                      f2h2(pb[2*i+1].x, pb[2*i+1].y), f2h2(pb[2*i+1].z, pb[2*i+1].w));
                *(uint4*)&Bn[lw + i * 4] = wb;
            }
        }
        __syncthreads();
    }

#pragma unroll
    for (int mt = 0; mt < 4; mt++) {
        const int r0 = m0 + wm + mt * 16 + g;
#pragma unroll
        for (int nt = 0; nt < 4; nt++) {
            const int c = n0 + wn + nt * 8 + tg * 2;
            *(uint32_t*)&C[(size_t)r0 * N + c]       = f2h2(acc[mt][nt][0] * cs, acc[mt][nt][1] * cs);
            *(uint32_t*)&C[(size_t)(r0 + 8) * N + c] = f2h2(acc[mt][nt][2] * cs, acc[mt][nt][3] * cs);
        }
    }
}

// ================= Projection GEMM: C[M,N] = Ah[M,K](fp16) * B[N,K]^T(fp32), fp32 out =================
__global__ __launch_bounds__(256, 2)
void gemm_proj(const __half* __restrict__ Ah, const float* __restrict__ B,
               float* __restrict__ C, int M, int N, int K)
{
    __shared__ uint32_t As[2 * GW];
    __shared__ uint32_t Bs[2 * GW];

    const int tid  = threadIdx.x;
    const int wid  = tid >> 5;
    const int lane = tid & 31;
    const int g    = lane >> 2;
    const int tg   = lane & 3;
    const int wm   = (wid >> 2) * 64;
    const int wn   = (wid & 3) * 32;
    const int m0   = blockIdx.y * 128;
    const int n0   = blockIdx.x * 128;

    const int lrow = tid >> 1;
    const int lc   = (tid & 1) * 16;
    const int lw   = lrow * GS2 + (tid & 1) * 8;

    const __half* Ap = Ah + (size_t)(m0 + lrow) * K + lc;   // 16 halves per thread
    const float*  Bp = B + (size_t)(n0 + lrow) * K + lc;    // 16 floats per thread

    uint4  qa[2];
    float4 pb[4];
    qa[0] = *(const uint4*)(Ap);
    qa[1] = *(const uint4*)(Ap + 8);
#pragma unroll
    for (int i = 0; i < 4; i++) pb[i] = *(const float4*)(Bp + i * 4);

    *(uint4*)&As[lw]     = qa[0];
    *(uint4*)&As[lw + 4] = qa[1];
#pragma unroll
    for (int i = 0; i < 2; i++) {
        uint4 wb = make_uint4(f2h2(pb[2*i].x, pb[2*i].y),     f2h2(pb[2*i].z, pb[2*i].w),
                              f2h2(pb[2*i+1].x, pb[2*i+1].y), f2h2(pb[2*i+1].z, pb[2*i+1].w));
        *(uint4*)&Bs[lw + i * 4] = wb;
    }
    __syncthreads();

    float acc[4][4][4] = {};
    const int T = K / 32;

    for (int t = 0; t < T; t++) {
        const int b = t & 1;
        const uint32_t* Ab = As + b * GW;
        const uint32_t* Bb = Bs + b * GW;

        if (t + 1 < T) {
            qa[0] = *(const uint4*)(Ap + (t + 1) * 32);
            qa[1] = *(const uint4*)(Ap + (t + 1) * 32 + 8);
#pragma unroll
            for (int i = 0; i < 4; i++) pb[i] = *(const float4*)(Bp + (t + 1) * 32 + i * 4);
        }

#pragma unroll
        for (int ks = 0; ks < 2; ks++) {
            const int k0 = ks * 8;
            uint32_t af[4][4];
#pragma unroll
            for (int mt = 0; mt < 4; mt++) {
                const int r = wm + mt * 16 + g;
                af[mt][0] = Ab[r * GS2 + k0 + tg];
                af[mt][1] = Ab[(r + 8) * GS2 + k0 + tg];
                af[mt][2] = Ab[r * GS2 + k0 + tg + 4];
                af[mt][3] = Ab[(r + 8) * GS2 + k0 + tg + 4];
            }
#pragma unroll
            for (int nt = 0; nt < 4; nt++) {
                const int rn = wn + nt * 8 + g;
                uint32_t b0 = Bb[rn * GS2 + k0 + tg];
                uint32_t b1 = Bb[rn * GS2 + k0 + tg + 4];
#pragma unroll
                for (int mt = 0; mt < 4; mt++)
                    mma16(acc[mt][nt], af[mt][0], af[mt][1], af[mt][2], af[mt][3], b0, b1);
            }
        }

        if (t + 1 < T) {
            uint32_t* An = As + (b ^ 1) * GW;
            uint32_t* Bn = Bs + (b ^ 1) * GW;
            *(uint4*)&An[lw]     = qa[0];
            *(uint4*)&An[lw + 4] = qa[1];
#pragma unroll
            for (int i = 0; i < 2; i++) {
                uint4 wb = make_uint4(f2h2(pb[2*i].x, pb[2*i].y),     f2h2(pb[2*i].z, pb[2*i].w),
                                      f2h2(pb[2*i+1].x, pb[2*i+1].y), f2h2(pb[2*i+1].z, pb[2*i+1].w));
                *(uint4*)&Bn[lw + i * 4] = wb;
            }
        }
        __syncthreads();
    }

#pragma unroll
    for (int mt = 0; mt < 4; mt++) {
        const int r0 = m0 + wm + mt * 16 + g;
#pragma unroll
        for (int nt = 0; nt < 4; nt++) {
            const int c = n0 + wn + nt * 8 + tg * 2;
            *(float2*)&C[(size_t)r0 * N + c]       = make_float2(acc[mt][nt][0], acc[mt][nt][1]);
            *(float2*)&C[(size_t)(r0 + 8) * N + c] = make_float2(acc[mt][nt][2], acc[mt][nt][3]);
        }
    }
}

// ================= V transpose (fp16 -> fp16) + queue reset =================
__global__ __launch_bounds__(256)
void transpose_v(const __half* __restrict__ V, __half* __restrict__ Vt)
{
    if (blockIdx.x == 0 && blockIdx.y == 0 && threadIdx.x == 0)
        g_unit_ctr = 0;

    __shared__ __half t[32][34];
    const int bx = blockIdx.x * 32;   // d
    const int by = blockIdx.y * 32;   // s
    const int tx = threadIdx.x & 31;
    const int ty = threadIdx.x >> 5;
#pragma unroll
    for (int i = 0; i < 32; i += 8)
        t[ty + i][tx] = V[(size_t)(by + ty + i) * DM + bx + tx];
    __syncthreads();
#pragma unroll
    for (int i = 0; i < 32; i += 8)
        Vt[(size_t)(bx + ty + i) * SEQ + by + tx] = t[tx][ty + i];
}

// ================= Flash attention (all-fp16 I/O, cp.async, persistent LPT queue) =================
#define FS 36
#define SM_Q  0
#define SM_K  (128 * FS)                 // 4608
#define SM_V  (SM_K + 2 * 64 * FS)       // 13824
#define SM_P  (SM_V + 2 * 64 * FS)       // 23040... (word offsets)
#define KVW   (64 * FS)                  // words per K or V buffer
#define FLASH_SMEM_WORDS (SM_P + 128 * FS)   // 18432 words = 73728 B
#define N_UNITS (32 * NH)                // 384
#define FLASH_GRID 296

__global__ __launch_bounds__(128, 2)
void flash_tc(const __half* __restrict__ Qh, const __half* __restrict__ Kh,
              const __half* __restrict__ Vt, __half* __restrict__ O)
{
    extern __shared__ uint32_t sm[];
    __shared__ int s_unit;
    uint32_t* Qs = sm + SM_Q;
    uint32_t* Ks = sm + SM_K;
    uint32_t* Vs = sm + SM_V;
    uint32_t* Ps = sm + SM_P;

    const uint32_t qs_a = smem_u32(Qs);
    const uint32_t ks_a = smem_u32(Ks);
    const uint32_t vs_a = smem_u32(Vs);

    const int tid  = threadIdx.x;
    const int lane = tid & 31;
    const int g    = lane >> 2;
    const int tg   = lane & 3;
    const int wm   = (tid >> 5) * 32;

    const int krow = tid >> 1;          // 0..63
    const int kch  = (tid & 1) * 32;    // half offset within 64-wide row
    const int kww  = (tid & 1) * 16;    // word offset within smem row

    for (;;) {
        if (tid == 0) s_unit = atomicAdd(&g_unit_ctr, 1);
        __syncthreads();                 // publish s_unit; prior unit's smem reads complete
        const int u = s_unit;
        if (u >= N_UNITS) return;
        const int qt = 31 - u / NH;      // longest-first
        const int h  = u % NH;

        const __half* krow_p = Kh + (size_t)krow * DM + h * HD + kch;          // + j*64*DM
        const __half* vrow_p = Vt + (size_t)(h * HD + krow) * SEQ + kch;       // + j*64

        // ---- prologue: async-copy Q tile + K/V tile 0 into buffer 0 ----
        {
            const __half* qrow = Qh + (size_t)(qt * 128 + tid) * DM + h * HD;
#pragma unroll
            for (int i = 0; i < 8; i++)
                CP_ASYNC16(qs_a + (tid * FS + i * 4) * 4, qrow + i * 8);
#pragma unroll
            for (int i = 0; i < 4; i++) {
                CP_ASYNC16(ks_a + (krow * FS + kww + i * 4) * 4, krow_p + i * 8);
                CP_ASYNC16(vs_a + (krow * FS + kww + i * 4) * 4, vrow_p + i * 8);
            }
            CP_COMMIT();
        }

        float o[2][8][4] = {};
        float m_[4], l_[4];
#pragma unroll
        for (int i = 0; i < 4; i++) { m_[i] = -1e30f; l_[i] = 0.0f; }

        const int jmax = 2 * qt + 1;

        for (int j = 0; j <= jmax; j++) {
            const int b = j & 1;
            const uint32_t* Kb = Ks + b * KVW;
            const uint32_t* Vb = Vs + b * KVW;

            CP_WAIT0();
            __syncthreads();   // tile j visible to all; all buf^1 readers (iter j-1) done

            // ---- issue async copy of tile j+1 into the other buffer ----
            if (j < jmax) {
                const uint32_t kd = ks_a + ((b ^ 1) * KVW + krow * FS + kww) * 4;
                const uint32_t vd = vs_a + ((b ^ 1) * KVW + krow * FS + kww) * 4;
                const __half* ksrc = krow_p + (size_t)(j + 1) * 64 * DM;
                const __half* vsrc = vrow_p + (size_t)(j + 1) * 64;
#pragma unroll
                for (int i = 0; i < 4; i++) {
                    CP_ASYNC16(kd + i * 16, ksrc + i * 8);
                    CP_ASYNC16(vd + i * 16, vsrc + i * 8);
                }
                CP_COMMIT();
            }

            // ---- S = Q K^T (4 k16 chunks) ----
            float sv[2][8][4] = {};
#pragma unroll
            for (int ck = 0; ck < 4; ck++) {
                const int k0 = ck * 8;
                uint32_t a[2][4];
#pragma unroll
                for (int mb = 0; mb < 2; mb++) {
                    const int r = wm + mb * 16 + g;
                    a[mb][0] = Qs[r * FS + k0 + tg];
                    a[mb][1] = Qs[(r + 8) * FS + k0 + tg];
                    a[mb][2] = Qs[r * FS + k0 + tg + 4];
                    a[mb][3] = Qs[(r + 8) * FS + k0 + tg + 4];
                }
#pragma unroll
                for (int nt = 0; nt < 8; nt++) {
                    uint32_t b0 = Kb[(nt * 8 + g) * FS + k0 + tg];
                    uint32_t b1 = Kb[(nt * 8 + g) * FS + k0 + tg + 4];
                    mma16(sv[0][nt], a[0][0], a[0][1], a[0][2], a[0][3], b0, b1);
                    mma16(sv[1][nt], a[1][0], a[1][1], a[1][2], a[1][3], b0, b1);
                }
            }

            // ---- causal mask ----
            if (j >= 2 * qt) {
                const int cb = j * 64;
#pragma unroll
                for (int mb = 0; mb < 2; mb++) {
                    const int r0 = qt * 128 + wm + mb * 16 + g, r1 = r0 + 8;
#pragma unroll
                    for (int nt = 0; nt < 8; nt++) {
#pragma unroll
                        for (int cc = 0; cc < 2; cc++) {
                            const int col = cb + nt * 8 + tg * 2 + cc;
                            if (col > r0) sv[mb][nt][cc]     = -1e30f;
                            if (col > r1) sv[mb][nt][2 + cc] = -1e30f;
                        }
                    }
                }
            }

            // ---- online softmax (base-2) ----
#pragma unroll
            for (int mb = 0; mb < 2; mb++) {
                float mx0 = -1e30f, mx1 = -1e30f;
#pragma unroll
                for (int nt = 0; nt < 8; nt++) {
                    mx0 = fmaxf(mx0, fmaxf(sv[mb][nt][0], sv[mb][nt][1]));
                    mx1 = fmaxf(mx1, fmaxf(sv[mb][nt][2], sv[mb][nt][3]));
                }
                mx0 = fmaxf(mx0, __shfl_xor_sync(0xffffffffu, mx0, 1));
                mx0 = fmaxf(mx0, __shfl_xor_sync(0xffffffffu, mx0, 2));
                mx1 = fmaxf(mx1, __shfl_xor_sync(0xffffffffu, mx1, 1));
                mx1 = fmaxf(mx1, __shfl_xor_sync(0xffffffffu, mx1, 2));

                const int g0 = 2 * mb, g1 = 2 * mb + 1;
                const float mn0 = fmaxf(m_[g0], mx0), mn1 = fmaxf(m_[g1], mx1);
                const float al0 = fexp2(m_[g0] - mn0), al1 = fexp2(m_[g1] - mn1);
                float s0 = 0.0f, s1 = 0.0f;
#pragma unroll
                for (int nt = 0; nt < 8; nt++) {
                    sv[mb][nt][0] = fexp2(sv[mb][nt][0] - mn0); s0 += sv[mb][nt][0];
                    sv[mb][nt][1] = fexp2(sv[mb][nt][1] - mn0); s0 += sv[mb][nt][1];
                    sv[mb][nt][2] = fexp2(sv[mb][nt][2] - mn1); s1 += sv[mb][nt][2];
                    sv[mb][nt][3] = fexp2(sv[mb][nt][3] - mn1); s1 += sv[mb][nt][3];
                }
                s0 += __shfl_xor_sync(0xffffffffu, s0, 1);
                s0 += __shfl_xor_sync(0xffffffffu, s0, 2);
                s1 += __shfl_xor_sync(0xffffffffu, s1, 1);
                s1 += __shfl_xor_sync(0xffffffffu, s1, 2);
                l_[g0] = l_[g0] * al0 + s0;  l_[g1] = l_[g1] * al1 + s1;
                m_[g0] = mn0;  m_[g1] = mn1;
#pragma unroll
                for (int nt = 0; nt < 8; nt++) {
                    o[mb][nt][0] *= al0; o[mb][nt][1] *= al0;
                    o[mb][nt][2] *= al1; o[mb][nt][3] *= al1;
                }
            }

            // ---- P to smem (warp-local rows) ----
#pragma unroll
            for (int mb = 0; mb < 2; mb++) {
                const int r = wm + mb * 16 + g;
#pragma unroll
                for (int nt = 0; nt < 8; nt++) {
                    Ps[r * FS + nt * 4 + tg]       = f2h2(sv[mb][nt][0], sv[mb][nt][1]);
                    Ps[(r + 8) * FS + nt * 4 + tg] = f2h2(sv[mb][nt][2], sv[mb][nt][3]);
                }
            }
            __syncwarp();

            // ---- O += P V ----
#pragma unroll
            for (int ck = 0; ck < 4; ck++) {
                const int k0 = ck * 8;
                uint32_t a[2][4];
#pragma unroll
                for (int mb = 0; mb < 2; mb++) {
                    const int r = wm + mb * 16 + g;
                    a[mb][0] = Ps[r * FS + k0 + tg];
                    a[mb][1] = Ps[(r + 8) * FS + k0 + tg];
                    a[mb][2] = Ps[r * FS + k0 + tg + 4];
                    a[mb][3] = Ps[(r + 8) * FS + k0 + tg + 4];
                }
#pragma unroll
                for (int nt = 0; nt < 8; nt++) {
                    uint32_t b0 = Vb[(nt * 8 + g) * FS + k0 + tg];
                    uint32_t b1 = Vb[(nt * 8 + g) * FS + k0 + tg + 4];
                    mma16(o[0][nt], a[0][0], a[0][1], a[0][2], a[0][3], b0, b1);
                    mma16(o[1][nt], a[1][0], a[1][1], a[1][2], a[1][3], b0, b1);
                }
            }
            // no end sync: next iter's top sync orders buf reuse
        }

        // ---- normalize + store (fp16) ----
#pragma unroll
        for (int mb = 0; mb < 2; mb++) {
            const float i0 = 1.0f / l_[2 * mb], i1 = 1.0f / l_[2 * mb + 1];
            const int r0 = qt * 128 + wm + mb * 16 + g, r1 = r0 + 8;
#pragma unroll
            for (int nt = 0; nt < 8; nt++) {
                const int c = h * HD + nt * 8 + tg * 2;
                *(uint32_t*)&O[(size_t)r0 * DM + c] = f2h2(o[mb][nt][0] * i0, o[mb][nt][1] * i0);
                *(uint32_t*)&O[(size_t)r1 * DM + c] = f2h2(o[mb][nt][2] * i1, o[mb][nt][3] * i1);
            }
        }
    }
}

// ================= launch =================
extern "C" void kernel_launch(void* const* d_in, const int* in_sizes, int n_in,
                              void* d_out, int out_size)
{
    (void)in_sizes; (void)n_in; (void)out_size;
    const float* x  = (const float*)d_in[0];
    const float* Wq = (const float*)d_in[1];
    const float* Wk = (const float*)d_in[2];
    const float* Wv = (const float*)d_in[3];
    const float* Wp = (const float*)d_in[4];
    float* out = (float*)d_out;

    __half *Qh, *Kh, *Vh, *Vt, *att;
    cudaGetSymbolAddress((void**)&Qh,  g_Qh);
    cudaGetSymbolAddress((void**)&Kh,  g_Kh);
    cudaGetSymbolAddress((void**)&Vh,  g_Vh);
    cudaGetSymbolAddress((void**)&Vt,  g_Vt);
    cudaGetSymbolAddress((void**)&att, g_att);

    const int flash_smem = FLASH_SMEM_WORDS * (int)sizeof(uint32_t);  // 73728 B
    cudaFuncSetAttribute(flash_tc, cudaFuncAttributeMaxDynamicSharedMemorySize, flash_smem);

    // fused QKV projection -> fp16 (Q pre-scaled)
    dim3 gq(DM / 128, SEQ / 128, 3);
    gemm_qkv<<<gq, 256>>>(x, Wq, Wk, Wv, Qh, Kh, Vh, SEQ, DM, DM);

    // transpose V -> fp16 [D][S] (+ reset flash work queue)
    dim3 gt(DM / 32, SEQ / 32);
    transpose_v<<<gt, 256>>>(Vh, Vt);

    // causal flash attention: persistent LPT queue, cp.async pipeline
    flash_tc<<<FLASH_GRID, 128, flash_smem>>>(Qh, Kh, Vt, att);

    // output projection (fp16 A)
    dim3 gp(DM / 128, SEQ / 128, 1);
    gemm_proj<<<gp, 256>>>(att, Wp, out, SEQ, DM, DM);
}

// round 10
// speedup vs baseline: 2.1932x; 1.1284x over previous
#include <cuda_runtime.h>
#include <cuda_fp16.h>
#include <cstdint>

#define SEQ 4096
#define DM  768
#define NH  12
#define HD  64

// ---------------- scratch (no allocations allowed) ----------------
__device__ __half g_Qh[SEQ * DM];    // Q fp16, pre-scaled by 0.125*log2e
__device__ __half g_Kh[SEQ * DM];    // K fp16
__device__ __half g_Vh[SEQ * DM];    // V fp16 [s][d]
__device__ __half g_Vt[DM * SEQ];    // V fp16 transposed [d][s]
__device__ __half g_att[SEQ * DM];   // attention output fp16
__device__ int    g_unit_ctr;        // flash work-queue counter (reset by transpose_v)

// ---------------- helpers ----------------
__device__ __forceinline__ uint32_t f2h2(float lo, float hi) {
    uint32_t r;
    asm("cvt.rn.f16x2.f32 %0, %2, %1;" : "=r"(r) : "f"(lo), "f"(hi));
    return r;
}
__device__ __forceinline__ float fexp2(float x) {
    float y;
    asm("ex2.approx.ftz.f32 %0, %1;" : "=f"(y) : "f"(x));
    return y;
}
__device__ __forceinline__ uint32_t smem_u32(const void* p) {
    uint32_t a;
    asm("{ .reg .u64 t; cvta.to.shared.u64 t, %1; cvt.u32.u64 %0, t; }" : "=r"(a) : "l"(p));
    return a;
}
__device__ __forceinline__ void ldsm4(uint32_t& r0, uint32_t& r1, uint32_t& r2, uint32_t& r3,
                                      uint32_t addr) {
    asm volatile("ldmatrix.sync.aligned.m8n8.x4.shared.b16 {%0,%1,%2,%3}, [%4];"
                 : "=r"(r0), "=r"(r1), "=r"(r2), "=r"(r3) : "r"(addr));
}
#define CP_ASYNC16(dst, src) \
    asm volatile("cp.async.ca.shared.global [%0], [%1], 16;" :: "r"(dst), "l"(src) : "memory")
#define CP_COMMIT() asm volatile("cp.async.commit_group;" ::: "memory")
#define CP_WAIT0()  asm volatile("cp.async.wait_group 0;" ::: "memory")

// D += A*B  (m16n8k16 fp16, fp32 accumulate)
__device__ __forceinline__ void mma16(float* d,
                                      uint32_t a0, uint32_t a1, uint32_t a2, uint32_t a3,
                                      uint32_t b0, uint32_t b1) {
    asm volatile(
        "mma.sync.aligned.m16n8k16.row.col.f32.f16.f16.f32 "
        "{%0,%1,%2,%3}, {%4,%5,%6,%7}, {%8,%9}, {%0,%1,%2,%3};"
        : "+f"(d[0]), "+f"(d[1]), "+f"(d[2]), "+f"(d[3])
        : "r"(a0), "r"(a1), "r"(a2), "r"(a3), "r"(b0), "r"(b1));
}

#define QK_SCALE 0.1803368801111204f   // 0.125 * log2(e)

// ================= QKV GEMM =================
#define GS2 20
#define GW  (128 * GS2)

__global__ __launch_bounds__(256, 2)
void gemm_qkv(const float* __restrict__ A,
              const float* __restrict__ B0, const float* __restrict__ B1, const float* __restrict__ B2,
              __half* __restrict__ C0, __half* __restrict__ C1, __half* __restrict__ C2,
              int M, int N, int K)
{
    const float* B = (blockIdx.z == 0) ? B0 : ((blockIdx.z == 1) ? B1 : B2);
    __half*      C = (blockIdx.z == 0) ? C0 : ((blockIdx.z == 1) ? C1 : C2);
    const float  cs = (blockIdx.z == 0) ? QK_SCALE : 1.0f;

    __shared__ __align__(16) uint32_t As[2 * GW];
    __shared__ __align__(16) uint32_t Bs[2 * GW];
    const uint32_t as_a = smem_u32(As);
    const uint32_t bs_a = smem_u32(Bs);

    const int tid  = threadIdx.x;
    const int wid  = tid >> 5;
    const int lane = tid & 31;
    const int g    = lane >> 2;
    const int tg   = lane & 3;
    const int wm   = (wid >> 2) * 64;
    const int wn   = (wid & 3) * 32;
    const int m0   = blockIdx.y * 128;
    const int n0   = blockIdx.x * 128;

    // ldmatrix per-thread word offsets
    const int aoff = (wm + (lane & 15)) * GS2 + ((lane >> 4) << 2);
    const int boff = (wn + ((lane >> 4) << 3) + (lane & 7)) * GS2 + (((lane >> 3) & 1) << 2);

    const int lrow = tid >> 1;
    const int lc   = (tid & 1) * 16;
    const int lw   = lrow * GS2 + (tid & 1) * 8;

    const float* Ap = A + (size_t)(m0 + lrow) * K + lc;
    const float* Bp = B + (size_t)(n0 + lrow) * K + lc;

    float4 pa[4], pb[4];
#pragma unroll
    for (int i = 0; i < 4; i++) {
        pa[i] = *(const float4*)(Ap + i * 4);
        pb[i] = *(const float4*)(Bp + i * 4);
    }
#pragma unroll
    for (int i = 0; i < 2; i++) {
        uint4 wa = make_uint4(f2h2(pa[2*i].x, pa[2*i].y),     f2h2(pa[2*i].z, pa[2*i].w),
                              f2h2(pa[2*i+1].x, pa[2*i+1].y), f2h2(pa[2*i+1].z, pa[2*i+1].w));
        *(uint4*)&As[lw + i * 4] = wa;
        uint4 wb = make_uint4(f2h2(pb[2*i].x, pb[2*i].y),     f2h2(pb[2*i].z, pb[2*i].w),
                              f2h2(pb[2*i+1].x, pb[2*i+1].y), f2h2(pb[2*i+1].z, pb[2*i+1].w));
        *(uint4*)&Bs[lw + i * 4] = wb;
    }
    __syncthreads();

    float acc[4][4][4] = {};
    const int T = K / 32;

    for (int t = 0; t < T; t++) {
        const int b = t & 1;
        const uint32_t ab = as_a + b * GW * 4;
        const uint32_t bb = bs_a + b * GW * 4;

        if (t + 1 < T) {
#pragma unroll
            for (int i = 0; i < 4; i++) {
                pa[i] = *(const float4*)(Ap + (t + 1) * 32 + i * 4);
                pb[i] = *(const float4*)(Bp + (t + 1) * 32 + i * 4);
            }
        }

#pragma unroll
        for (int ks = 0; ks < 2; ks++) {
            const int k0 = ks * 8;
            uint32_t af[4][4], bf[2][4];
#pragma unroll
            for (int mt = 0; mt < 4; mt++)
                ldsm4(af[mt][0], af[mt][1], af[mt][2], af[mt][3],
                      ab + (aoff + mt * 16 * GS2 + k0) * 4);
#pragma unroll
            for (int np = 0; np < 2; np++)
                ldsm4(bf[np][0], bf[np][1], bf[np][2], bf[np][3],
                      bb + (boff + np * 16 * GS2 + k0) * 4);
#pragma unroll
            for (int nt = 0; nt < 4; nt++) {
                const uint32_t b0 = bf[nt >> 1][(nt & 1) * 2];
                const uint32_t b1 = bf[nt >> 1][(nt & 1) * 2 + 1];
#pragma unroll
                for (int mt = 0; mt < 4; mt++)
                    mma16(acc[mt][nt], af[mt][0], af[mt][1], af[mt][2], af[mt][3], b0, b1);
            }
        }

        if (t + 1 < T) {
            uint32_t* An = As + (b ^ 1) * GW;
            uint32_t* Bn = Bs + (b ^ 1) * GW;
#pragma unroll
            for (int i = 0; i < 2; i++) {
                uint4 wa = make_uint4(f2h2(pa[2*i].x, pa[2*i].y),     f2h2(pa[2*i].z, pa[2*i].w),
                                      f2h2(pa[2*i+1].x, pa[2*i+1].y), f2h2(pa[2*i+1].z, pa[2*i+1].w));
                *(uint4*)&An[lw + i * 4] = wa;
                uint4 wb = make_uint4(f2h2(pb[2*i].x, pb[2*i].y),     f2h2(pb[2*i].z, pb[2*i].w),
                                      f2h2(pb[2*i+1].x, pb[2*i+1].y), f2h2(pb[2*i+1].z, pb[2*i+1].w));
                *(uint4*)&Bn[lw + i * 4] = wb;
            }
        }
        __syncthreads();
    }

#pragma unroll
    for (int mt = 0; mt < 4; mt++) {
        const int r0 = m0 + wm + mt * 16 + g;
#pragma unroll
        for (int nt = 0; nt < 4; nt++) {
            const int c = n0 + wn + nt * 8 + tg * 2;
            *(uint32_t*)&C[(size_t)r0 * N + c]       = f2h2(acc[mt][nt][0] * cs, acc[mt][nt][1] * cs);
            *(uint32_t*)&C[(size_t)(r0 + 8) * N + c] = f2h2(acc[mt][nt][2] * cs, acc[mt][nt][3] * cs);
        }
    }
}

// ================= Projection GEMM =================
__global__ __launch_bounds__(256, 2)
void gemm_proj(const __half* __restrict__ Ah, const float* __restrict__ B,
               float* __restrict__ C, int M, int N, int K)
{
    __shared__ __align__(16) uint32_t As[2 * GW];
    __shared__ __align__(16) uint32_t Bs[2 * GW];
    const uint32_t as_a = smem_u32(As);
    const uint32_t bs_a = smem_u32(Bs);

    const int tid  = threadIdx.x;
    const int wid  = tid >> 5;
    const int lane = tid & 31;
    const int g    = lane >> 2;
    const int tg   = lane & 3;
    const int wm   = (wid >> 2) * 64;
    const int wn   = (wid & 3) * 32;
    const int m0   = blockIdx.y * 128;
    const int n0   = blockIdx.x * 128;

    const int aoff = (wm + (lane & 15)) * GS2 + ((lane >> 4) << 2);
    const int boff = (wn + ((lane >> 4) << 3) + (lane & 7)) * GS2 + (((lane >> 3) & 1) << 2);

    const int lrow = tid >> 1;
    const int lc   = (tid & 1) * 16;
    const int lw   = lrow * GS2 + (tid & 1) * 8;

    const __half* Ap = Ah + (size_t)(m0 + lrow) * K + lc;
    const float*  Bp = B + (size_t)(n0 + lrow) * K + lc;

    uint4  qa[2];
    float4 pb[4];
    qa[0] = *(const uint4*)(Ap);
    qa[1] = *(const uint4*)(Ap + 8);
#pragma unroll
    for (int i = 0; i < 4; i++) pb[i] = *(const float4*)(Bp + i * 4);

    *(uint4*)&As[lw]     = qa[0];
    *(uint4*)&As[lw + 4] = qa[1];
#pragma unroll
    for (int i = 0; i < 2; i++) {
        uint4 wb = make_uint4(f2h2(pb[2*i].x, pb[2*i].y),     f2h2(pb[2*i].z, pb[2*i].w),
                              f2h2(pb[2*i+1].x, pb[2*i+1].y), f2h2(pb[2*i+1].z, pb[2*i+1].w));
        *(uint4*)&Bs[lw + i * 4] = wb;
    }
    __syncthreads();

    float acc[4][4][4] = {};
    const int T = K / 32;

    for (int t = 0; t < T; t++) {
        const int b = t & 1;
        const uint32_t ab = as_a + b * GW * 4;
        const uint32_t bb = bs_a + b * GW * 4;

        if (t + 1 < T) {
            qa[0] = *(const uint4*)(Ap + (t + 1) * 32);
            qa[1] = *(const uint4*)(Ap + (t + 1) * 32 + 8);
#pragma unroll
            for (int i = 0; i < 4; i++) pb[i] = *(const float4*)(Bp + (t + 1) * 32 + i * 4);
        }

#pragma unroll
        for (int ks = 0; ks < 2; ks++) {
            const int k0 = ks * 8;
            uint32_t af[4][4], bf[2][4];
#pragma unroll
            for (int mt = 0; mt < 4; mt++)
                ldsm4(af[mt][0], af[mt][1], af[mt][2], af[mt][3],
                      ab + (aoff + mt * 16 * GS2 + k0) * 4);
#pragma unroll
            for (int np = 0; np < 2; np++)
                ldsm4(bf[np][0], bf[np][1], bf[np][2], bf[np][3],
                      bb + (boff + np * 16 * GS2 + k0) * 4);
#pragma unroll
            for (int nt = 0; nt < 4; nt++) {
                const uint32_t b0 = bf[nt >> 1][(nt & 1) * 2];
                const uint32_t b1 = bf[nt >> 1][(nt & 1) * 2 + 1];
#pragma unroll
                for (int mt = 0; mt < 4; mt++)
                    mma16(acc[mt][nt], af[mt][0], af[mt][1], af[mt][2], af[mt][3], b0, b1);
            }
        }

        if (t + 1 < T) {
            uint32_t* An = As + (b ^ 1) * GW;
            uint32_t* Bn = Bs + (b ^ 1) * GW;
            *(uint4*)&An[lw]     = qa[0];
            *(uint4*)&An[lw + 4] = qa[1];
#pragma unroll
            for (int i = 0; i < 2; i++) {
                uint4 wb = make_uint4(f2h2(pb[2*i].x, pb[2*i].y),     f2h2(pb[2*i].z, pb[2*i].w),
                                      f2h2(pb[2*i+1].x, pb[2*i+1].y), f2h2(pb[2*i+1].z, pb[2*i+1].w));
                *(uint4*)&Bn[lw + i * 4] = wb;
            }
        }
        __syncthreads();
    }

#pragma unroll
    for (int mt = 0; mt < 4; mt++) {
        const int r0 = m0 + wm + mt * 16 + g;
#pragma unroll
        for (int nt = 0; nt < 4; nt++) {
            const int c = n0 + wn + nt * 8 + tg * 2;
            *(float2*)&C[(size_t)r0 * N + c]       = make_float2(acc[mt][nt][0], acc[mt][nt][1]);
            *(float2*)&C[(size_t)(r0 + 8) * N + c] = make_float2(acc[mt][nt][2], acc[mt][nt][3]);
        }
    }
}

// ================= V transpose (fp16) + queue reset =================
__global__ __launch_bounds__(256)
void transpose_v(const __half* __restrict__ V, __half* __restrict__ Vt)
{
    if (blockIdx.x == 0 && blockIdx.y == 0 && threadIdx.x == 0)
        g_unit_ctr = 0;

    __shared__ __half t[32][34];
    const int bx = blockIdx.x * 32;
    const int by = blockIdx.y * 32;
    const int tx = threadIdx.x & 31;
    const int ty = threadIdx.x >> 5;
#pragma unroll
    for (int i = 0; i < 32; i += 8)
        t[ty + i][tx] = V[(size_t)(by + ty + i) * DM + bx + tx];
    __syncthreads();
#pragma unroll
    for (int i = 0; i < 32; i += 8)
        Vt[(size_t)(bx + ty + i) * SEQ + by + tx] = t[tx][ty + i];
}

// ================= Flash attention (fp16, cp.async, persistent LPT, ldmatrix) =================
#define FS 36
#define SM_Q  0
#define SM_K  (128 * FS)
#define SM_V  (SM_K + 2 * 64 * FS)
#define SM_P  (SM_V + 2 * 64 * FS)
#define KVW   (64 * FS)
#define FLASH_SMEM_WORDS (SM_P + 128 * FS)   // 18432 words = 73728 B
#define N_UNITS (32 * NH)
#define FLASH_GRID 296

__global__ __launch_bounds__(128, 2)
void flash_tc(const __half* __restrict__ Qh, const __half* __restrict__ Kh,
              const __half* __restrict__ Vt, __half* __restrict__ O)
{
    extern __shared__ uint32_t sm[];
    __shared__ int s_unit;
    uint32_t* Qs = sm + SM_Q;
    uint32_t* Ks = sm + SM_K;
    uint32_t* Vs = sm + SM_V;
    uint32_t* Ps = sm + SM_P;

    const uint32_t qs_a = smem_u32(Qs);
    const uint32_t ks_a = smem_u32(Ks);
    const uint32_t vs_a = smem_u32(Vs);
    const uint32_t ps_a = smem_u32(Ps);

    const int tid  = threadIdx.x;
    const int lane = tid & 31;
    const int g    = lane >> 2;
    const int tg   = lane & 3;
    const int wm   = (tid >> 5) * 32;

    const int krow = tid >> 1;
    const int kch  = (tid & 1) * 32;
    const int kww  = (tid & 1) * 16;

    // ldmatrix per-thread word offsets (FS stride)
    const int a_off = (wm + (lane & 15)) * FS + ((lane >> 4) << 2);         // A-type (Q, P)
    const int b_off = (((lane >> 4) << 3) + (lane & 7)) * FS + (((lane >> 3) & 1) << 2);  // B-type (K, V)

    for (;;) {
        if (tid == 0) s_unit = atomicAdd(&g_unit_ctr, 1);
        __syncthreads();
        const int u = s_unit;
        if (u >= N_UNITS) return;
        const int qt = 31 - u / NH;
        const int h  = u % NH;

        const __half* krow_p = Kh + (size_t)krow * DM + h * HD + kch;
        const __half* vrow_p = Vt + (size_t)(h * HD + krow) * SEQ + kch;

        {
            const __half* qrow = Qh + (size_t)(qt * 128 + tid) * DM + h * HD;
#pragma unroll
            for (int i = 0; i < 8; i++)
                CP_ASYNC16(qs_a + (tid * FS + i * 4) * 4, qrow + i * 8);
#pragma unroll
            for (int i = 0; i < 4; i++) {
                CP_ASYNC16(ks_a + (krow * FS + kww + i * 4) * 4, krow_p + i * 8);
                CP_ASYNC16(vs_a + (krow * FS + kww + i * 4) * 4, vrow_p + i * 8);
            }
            CP_COMMIT();
        }

        float o[2][8][4] = {};
        float m_[4], l_[4];
#pragma unroll
        for (int i = 0; i < 4; i++) { m_[i] = -1e30f; l_[i] = 0.0f; }

        const int jmax = 2 * qt + 1;

        for (int j = 0; j <= jmax; j++) {
            const int b = j & 1;
            const uint32_t kb = ks_a + b * KVW * 4;
            const uint32_t vb = vs_a + b * KVW * 4;

            CP_WAIT0();
            __syncthreads();

            if (j < jmax) {
                const uint32_t kd = ks_a + ((b ^ 1) * KVW + krow * FS + kww) * 4;
                const uint32_t vd = vs_a + ((b ^ 1) * KVW + krow * FS + kww) * 4;
                const __half* ksrc = krow_p + (size_t)(j + 1) * 64 * DM;
                const __half* vsrc = vrow_p + (size_t)(j + 1) * 64;
#pragma unroll
                for (int i = 0; i < 4; i++) {
                    CP_ASYNC16(kd + i * 16, ksrc + i * 8);
                    CP_ASYNC16(vd + i * 16, vsrc + i * 8);
                }
                CP_COMMIT();
            }

            // ---- S = Q K^T (ldmatrix fragments) ----
            float sv[2][8][4] = {};
#pragma unroll
            for (int ck = 0; ck < 4; ck++) {
                const int k0 = ck * 8;
                uint32_t a[2][4], bf[4][4];
#pragma unroll
                for (int mb = 0; mb < 2; mb++)
                    ldsm4(a[mb][0], a[mb][1], a[mb][2], a[mb][3],
                          qs_a + (a_off + mb * 16 * FS + k0) * 4);
#pragma unroll
                for (int np = 0; np < 4; np++)
                    ldsm4(bf[np][0], bf[np][1], bf[np][2], bf[np][3],
                          kb + (b_off + np * 16 * FS + k0) * 4);
#pragma unroll
                for (int nt = 0; nt < 8; nt++) {
                    const uint32_t b0 = bf[nt >> 1][(nt & 1) * 2];
                    const uint32_t b1 = bf[nt >> 1][(nt & 1) * 2 + 1];
                    mma16(sv[0][nt], a[0][0], a[0][1], a[0][2], a[0][3], b0, b1);
                    mma16(sv[1][nt], a[1][0], a[1][1], a[1][2], a[1][3], b0, b1);
                }
            }

            // ---- causal mask ----
            if (j >= 2 * qt) {
                const int cb = j * 64;
#pragma unroll
                for (int mb = 0; mb < 2; mb++) {
                    const int r0 = qt * 128 + wm + mb * 16 + g, r1 = r0 + 8;
#pragma unroll
                    for (int nt = 0; nt < 8; nt++) {
#pragma unroll
                        for (int cc = 0; cc < 2; cc++) {
                            const int col = cb + nt * 8 + tg * 2 + cc;
                            if (col > r0) sv[mb][nt][cc]     = -1e30f;
                            if (col > r1) sv[mb][nt][2 + cc] = -1e30f;
                        }
                    }
                }
            }

            // ---- online softmax (base-2) ----
#pragma unroll
            for (int mb = 0; mb < 2; mb++) {
                float mx0 = -1e30f, mx1 = -1e30f;
#pragma unroll
                for (int nt = 0; nt < 8; nt++) {
                    mx0 = fmaxf(mx0, fmaxf(sv[mb][nt][0], sv[mb][nt][1]));
                    mx1 = fmaxf(mx1, fmaxf(sv[mb][nt][2], sv[mb][nt][3]));
                }
                mx0 = fmaxf(mx0, __shfl_xor_sync(0xffffffffu, mx0, 1));
                mx0 = fmaxf(mx0, __shfl_xor_sync(0xffffffffu, mx0, 2));
                mx1 = fmaxf(mx1, __shfl_xor_sync(0xffffffffu, mx1, 1));
                mx1 = fmaxf(mx1, __shfl_xor_sync(0xffffffffu, mx1, 2));

                const int g0 = 2 * mb, g1 = 2 * mb + 1;
                const float mn0 = fmaxf(m_[g0], mx0), mn1 = fmaxf(m_[g1], mx1);
                const float al0 = fexp2(m_[g0] - mn0), al1 = fexp2(m_[g1] - mn1);
                float s0 = 0.0f, s1 = 0.0f;
#pragma unroll
                for (int nt = 0; nt < 8; nt++) {
                    sv[mb][nt][0] = fexp2(sv[mb][nt][0] - mn0); s0 += sv[mb][nt][0];
                    sv[mb][nt][1] = fexp2(sv[mb][nt][1] - mn0); s0 += sv[mb][nt][1];
                    sv[mb][nt][2] = fexp2(sv[mb][nt][2] - mn1); s1 += sv[mb][nt][2];
                    sv[mb][nt][3] = fexp2(sv[mb][nt][3] - mn1); s1 += sv[mb][nt][3];
                }
                s0 += __shfl_xor_sync(0xffffffffu, s0, 1);
                s0 += __shfl_xor_sync(0xffffffffu, s0, 2);
                s1 += __shfl_xor_sync(0xffffffffu, s1, 1);
                s1 += __shfl_xor_sync(0xffffffffu, s1, 2);
                l_[g0] = l_[g0] * al0 + s0;  l_[g1] = l_[g1] * al1 + s1;
                m_[g0] = mn0;  m_[g1] = mn1;
#pragma unroll
                for (int nt = 0; nt < 8; nt++) {
                    o[mb][nt][0] *= al0; o[mb][nt][1] *= al0;
                    o[mb][nt][2] *= al1; o[mb][nt][3] *= al1;
                }
            }

            // ---- P to smem (warp-local rows) ----
#pragma unroll
            for (int mb = 0; mb < 2; mb++) {
                const int r = wm + mb * 16 + g;
#pragma unroll
                for (int nt = 0; nt < 8; nt++) {
                    Ps[r * FS + nt * 4 + tg]       = f2h2(sv[mb][nt][0], sv[mb][nt][1]);
                    Ps[(r + 8) * FS + nt * 4 + tg] = f2h2(sv[mb][nt][2], sv[mb][nt][3]);
                }
            }
            __syncwarp();

            // ---- O += P V (ldmatrix fragments) ----
#pragma unroll
            for (int ck = 0; ck < 4; ck++) {
                const int k0 = ck * 8;
                uint32_t a[2][4], bf[4][4];
#pragma unroll
                for (int mb = 0; mb < 2; mb++)
                    ldsm4(a[mb][0], a[mb][1], a[mb][2], a[mb][3],
                          ps_a + (a_off + mb * 16 * FS + k0) * 4);
#pragma unroll
                for (int np = 0; np < 4; np++)
                    ldsm4(bf[np][0], bf[np][1], bf[np][2], bf[np][3],
                          vb + (b_off + np * 16 * FS + k0) * 4);
#pragma unroll
                for (int nt = 0; nt < 8; nt++) {
                    const uint32_t b0 = bf[nt >> 1][(nt & 1) * 2];
                    const uint32_t b1 = bf[nt >> 1][(nt & 1) * 2 + 1];
                    mma16(o[0][nt], a[0][0], a[0][1], a[0][2], a[0][3], b0, b1);
                    mma16(o[1][nt], a[1][0], a[1][1], a[1][2], a[1][3], b0, b1);
                }
            }
        }

        // ---- normalize + store (fp16) ----
#pragma unroll
        for (int mb = 0; mb < 2; mb++) {
            const float i0 = 1.0f / l_[2 * mb], i1 = 1.0f / l_[2 * mb + 1];
            const int r0 = qt * 128 + wm + mb * 16 + g, r1 = r0 + 8;
#pragma unroll
            for (int nt = 0; nt < 8; nt++) {
                const int c = h * HD + nt * 8 + tg * 2;
                *(uint32_t*)&O[(size_t)r0 * DM + c] = f2h2(o[mb][nt][0] * i0, o[mb][nt][1] * i0);
                *(uint32_t*)&O[(size_t)r1 * DM + c] = f2h2(o[mb][nt][2] * i1, o[mb][nt][3] * i1);
            }
        }
    }
}

// ================= launch =================
extern "C" void kernel_launch(void* const* d_in, const int* in_sizes, int n_in,
                              void* d_out, int out_size)
{
    (void)in_sizes; (void)n_in; (void)out_size;
    const float* x  = (const float*)d_in[0];
    const float* Wq = (const float*)d_in[1];
    const float* Wk = (const float*)d_in[2];
    const float* Wv = (const float*)d_in[3];
    const float* Wp = (const float*)d_in[4];
    float* out = (float*)d_out;

    __half *Qh, *Kh, *Vh, *Vt, *att;
    cudaGetSymbolAddress((void**)&Qh,  g_Qh);
    cudaGetSymbolAddress((void**)&Kh,  g_Kh);
    cudaGetSymbolAddress((void**)&Vh,  g_Vh);
    cudaGetSymbolAddress((void**)&Vt,  g_Vt);
    cudaGetSymbolAddress((void**)&att, g_att);

    const int flash_smem = FLASH_SMEM_WORDS * (int)sizeof(uint32_t);  // 73728 B
    cudaFuncSetAttribute(flash_tc, cudaFuncAttributeMaxDynamicSharedMemorySize, flash_smem);

    dim3 gq(DM / 128, SEQ / 128, 3);
    gemm_qkv<<<gq, 256>>>(x, Wq, Wk, Wv, Qh, Kh, Vh, SEQ, DM, DM);

    dim3 gt(DM / 32, SEQ / 32);
    transpose_v<<<gt, 256>>>(Vh, Vt);

    flash_tc<<<FLASH_GRID, 128, flash_smem>>>(Qh, Kh, Vt, att);

    dim3 gp(DM / 128, SEQ / 128, 1);
    gemm_proj<<<gp, 256>>>(att, Wp, out, SEQ, DM, DM);
}